// round 2
// baseline (speedup 1.0000x reference)
#include <cuda_runtime.h>
#include <math.h>

#define NU 100000
#define NI 50000
#define NE 800000
#define BB 1024

__device__ float g_Eu1[NU*64];
__device__ float g_Eu2[NU*64];
__device__ float g_EuS[NU*64];
__device__ float g_U1 [NU*64];
__device__ float g_Hg [NU*64];
__device__ float g_hu [NU*64];
__device__ float g_Zu [NU*64];
__device__ float g_Ei1[NI*64];
__device__ float g_Ei2[NI*64];
__device__ float g_EiS[NI*64];
__device__ float g_I1 [NI*64];
__device__ float g_hi [NI*64];
__device__ float g_Zi [NI*64];
__device__ float g_au[NU];
__device__ float g_ai[NI];
__device__ float g_views[4*NE];
__device__ float g_pre[NE];
__device__ float g_aug[NE];
__device__ int   g_rowptr_u[NU+1];
__device__ int   g_rowptr_i[NI+1];
__device__ int   g_cur_u[NU];
__device__ int   g_cur_i[NI];
__device__ int   g_deg_u[NU];
__device__ int   g_deg_i[NI];
__device__ int   g_col_u[NE];
__device__ int   g_eid_u[NE];
__device__ int   g_col_i[NE];
__device__ int   g_eid_i[NE];
__device__ double g_expsum[4];
__device__ double g_acc[4];     // 0: pr, 1: reg, 2: bpr, 3: pos
__device__ double g_negS[2*BB];

__device__ __forceinline__ float sigf(float x){ return 1.f/(1.f+expf(-x)); }

__global__ void k_init(){
  int i=blockIdx.x*blockDim.x+threadIdx.x, st=gridDim.x*blockDim.x;
  for(int t=i;t<NU;t+=st) g_deg_u[t]=0;
  for(int t=i;t<NI;t+=st) g_deg_i[t]=0;
  for(int t=i;t<2*BB;t+=st) g_negS[t]=0.0;
  if(i<4){ g_expsum[i]=0.0; g_acc[i]=0.0; }
}

__global__ void k_count(const int* __restrict__ src, const int* __restrict__ dst){
  int e=blockIdx.x*blockDim.x+threadIdx.x;
  if(e<NE){ atomicAdd(&g_deg_u[src[e]],1); atomicAdd(&g_deg_i[dst[e]],1); }
}

__global__ void k_scan(const int* __restrict__ deg, int* __restrict__ rowptr,
                       int* __restrict__ cur, int n){
  __shared__ int part[1024];
  int tid=threadIdx.x;
  int chunk=(n+1023)>>10;
  int s=tid*chunk, e=min(s+chunk,n);
  int sum=0;
  for(int i=s;i<e;i++) sum+=deg[i];
  part[tid]=sum; __syncthreads();
  for(int off=1;off<1024;off<<=1){
    int v=(tid>=off)?part[tid-off]:0;
    __syncthreads();
    part[tid]+=v;
    __syncthreads();
  }
  int run=part[tid]-sum;
  for(int i=s;i<e;i++){ rowptr[i]=run; cur[i]=run; run+=deg[i]; }
  if(tid==1023) rowptr[n]=part[1023];
}

__global__ void k_fill(const int* __restrict__ src, const int* __restrict__ dst){
  int e=blockIdx.x*blockDim.x+threadIdx.x;
  if(e<NE){
    int s=src[e], d=dst[e];
    int p=atomicAdd(&g_cur_u[s],1); g_col_u[p]=d; g_eid_u[p]=e;
    int q=atomicAdd(&g_cur_i[d],1); g_col_i[q]=s; g_eid_i[q]=e;
  }
}

// Y[r,:] = sum_j w_j * X[col_j,:]; w_j = vals[eid]*(optional dropout mask)
__global__ void k_spmm(const int* __restrict__ rowptr, const int* __restrict__ col,
                       const int* __restrict__ eid, const float* __restrict__ vals,
                       const float* __restrict__ drop, const float* __restrict__ X,
                       float* __restrict__ Y, int nrows){
  __shared__ int   sc[4][64];
  __shared__ float sv[4][64];
  __shared__ int   sdeg[4];
  int tx=threadIdx.x, ty=threadIdx.y;
  int r=blockIdx.x*4+ty;
  int beg=0,end=0;
  if(r<nrows){ beg=rowptr[r]; end=rowptr[r+1]; }
  int deg=end-beg;
  if(tx==0) sdeg[ty]=deg;
  __syncthreads();
  int maxdeg=max(max(sdeg[0],sdeg[1]),max(sdeg[2],sdeg[3]));
  float acc=0.f;
  for(int base=0; base<maxdeg; base+=64){
    int jj=base+tx;
    if(jj<deg){
      int j=beg+jj;
      int id=eid[j];
      float v=vals[id];
      if(drop) v=(drop[id]>0.25f)? v*1.3333333333333333f : 0.f;
      sc[ty][tx]=col[j]; sv[ty][tx]=v;
    }
    __syncthreads();
    int cnt=min(deg-base,64);
    for(int q=0;q<cnt;q++){
      float v=sv[ty][q];
      if(v!=0.f) acc += v * X[sc[ty][q]*64 + tx];
    }
    __syncthreads();
  }
  if(r<nrows) Y[r*64+tx]=acc;
}

__global__ void k_combine(const float* __restrict__ A, const float* __restrict__ Bv,
                          const float* __restrict__ C, float* __restrict__ O, int n){
  int i=blockIdx.x*blockDim.x+threadIdx.x;
  if(i<n) O[i]=A[i]+Bv[i]+C[i];
}

// Y = X @ W (+bias), [n,64]@[64,64]
__global__ void k_gemm_node(const float* __restrict__ X, const float* __restrict__ W,
                            const float* __restrict__ bias, float* __restrict__ Y, int n){
  __shared__ float Ws[64*64];
  __shared__ float Xs[4][64];
  int tx=threadIdx.x, ty=threadIdx.y;
  for(int t=ty*64+tx;t<4096;t+=256) Ws[t]=W[t];
  int r=blockIdx.x*4+ty;
  if(r<n) Xs[ty][tx]=X[r*64+tx];
  __syncthreads();
  if(r<n){
    float acc = bias ? bias[tx] : 0.f;
    #pragma unroll
    for(int k=0;k<64;k++) acc += Xs[ty][k]*Ws[k*64+tx];
    Y[r*64+tx]=acc;
  }
}

__global__ void k_att(const float* __restrict__ X, const float* __restrict__ a,
                      float* __restrict__ out, int n){
  int w=(blockIdx.x*blockDim.x+threadIdx.x)>>5;
  int l=threadIdx.x&31;
  if(w>=n) return;
  float s = X[w*64+l]*a[l] + X[w*64+l+32]*a[l+32];
  #pragma unroll
  for(int o=16;o;o>>=1) s += __shfl_xor_sync(0xffffffffu,s,o);
  if(l==0) out[w]=s;
}

__global__ void k_edge1(const int* __restrict__ src, const int* __restrict__ dst,
                        const float* __restrict__ W2, const float* __restrict__ b2,
                        const float* __restrict__ wv, const float* __restrict__ fw,
                        const float* __restrict__ fb){
  __shared__ float W2s[64];
  __shared__ double sacc[4];
  int tid=threadIdx.x;
  if(tid<64) W2s[tid]=W2[tid];
  if(tid<4)  sacc[tid]=0.0;
  __syncthreads();
  int gw=(blockIdx.x*blockDim.x+tid)>>5;
  int l=tid&31;
  if(gw<NE){
    int s=src[gw], t=dst[gw];
    int so=s*64, to=t*64;
    float m  = fmaxf(g_U1[so+l]+g_I1[to+l],0.f)*W2s[l]
             + fmaxf(g_U1[so+l+32]+g_I1[to+l+32],0.f)*W2s[l+32];
    float gc = g_Hg[so+l]*g_hi[to+l] + g_Hg[so+l+32]*g_hi[to+l+32];
    float pr = g_EuS[so+l]*g_EiS[to+l] + g_EuS[so+l+32]*g_EiS[to+l+32];
    #pragma unroll
    for(int o=16;o;o>>=1){
      m  += __shfl_xor_sync(0xffffffffu,m,o);
      gc += __shfl_xor_sync(0xffffffffu,gc,o);
      pr += __shfl_xor_sync(0xffffffffu,pr,o);
    }
    if(l==0){
      float v0=sigf(m+b2[0]);
      float v1=sigf(wv[gw]);
      float v2=sigf(gc);
      float a=g_au[s]+g_ai[t];
      float v3=sigf(a>0.f? a : 0.2f*a);
      g_views[gw]=v0; g_views[NE+gw]=v1; g_views[2*NE+gw]=v2; g_views[3*NE+gw]=v3;
      g_pre[gw]=sigf(pr);
      float w=fw[gw], b=fb[gw];
      atomicAdd(&sacc[0],(double)expf(tanhf(w*v0+b)));
      atomicAdd(&sacc[1],(double)expf(tanhf(w*v1+b)));
      atomicAdd(&sacc[2],(double)expf(tanhf(w*v2+b)));
      atomicAdd(&sacc[3],(double)expf(tanhf(w*v3+b)));
    }
  }
  __syncthreads();
  if(tid<4) atomicAdd(&g_expsum[tid],sacc[tid]);
}

__global__ void k_edge2(const float* __restrict__ fw, const float* __restrict__ fb,
                        const float* __restrict__ adj){
  int e=blockIdx.x*blockDim.x+threadIdx.x;
  float lp=0.f;
  if(e<NE){
    float S0=(float)g_expsum[0], S1=(float)g_expsum[1];
    float S2=(float)g_expsum[2], S3=(float)g_expsum[3];
    float w=fw[e], b=fb[e];
    float v0=g_views[e], v1=g_views[NE+e], v2=g_views[2*NE+e], v3=g_views[3*NE+e];
    float Ag = expf(tanhf(w*v0+b))/S0*v0
             + expf(tanhf(w*v1+b))/S1*v1
             + expf(tanhf(w*v2+b))/S2*v2
             + expf(tanhf(w*v3+b))/S3*v3;
    float sumv=v0+v1+v2+v3;
    float agf=(sumv-3.f*Ag)*0.2f;
    float baew=g_pre[e]*agf;
    g_aug[e]=baew*adj[e];
    lp=-logf(baew);
  }
  #pragma unroll
  for(int o=16;o;o>>=1) lp += __shfl_xor_sync(0xffffffffu,lp,o);
  if((threadIdx.x&31)==0) atomicAdd(&g_acc[0],(double)lp);
}

__global__ void k_sqsum(const float* __restrict__ p, int n){
  double s=0.0;
  for(int i=blockIdx.x*blockDim.x+threadIdx.x;i<n;i+=gridDim.x*blockDim.x){
    float v=p[i]; s+=(double)v*(double)v;
  }
  #pragma unroll
  for(int o=16;o;o>>=1) s += __shfl_xor_sync(0xffffffffu,s,o);
  if((threadIdx.x&31)==0) atomicAdd(&g_acc[1],s);
}

__global__ void k_small(const int* __restrict__ uids, const int* __restrict__ iids,
                        const int* __restrict__ pos, const int* __restrict__ neg){
  int w=(blockIdx.x*blockDim.x+threadIdx.x)>>5;
  int l=threadIdx.x&31;
  if(w>=BB) return;
  int u=uids[w], it=iids[w], p=pos[w], ng=neg[w];
  float dzu=0,dzi=0,dup=0,dun=0;
  #pragma unroll
  for(int d=l; d<64; d+=32){
    float eu=g_EuS[u*64+d];
    dzu += g_Zu[u*64+d]*eu;
    dzi += g_Zi[it*64+d]*g_EiS[it*64+d];
    dup += eu*g_EiS[p*64+d];
    dun += eu*g_EiS[ng*64+d];
  }
  #pragma unroll
  for(int o=16;o;o>>=1){
    dzu+=__shfl_xor_sync(0xffffffffu,dzu,o);
    dzi+=__shfl_xor_sync(0xffffffffu,dzi,o);
    dup+=__shfl_xor_sync(0xffffffffu,dup,o);
    dun+=__shfl_xor_sync(0xffffffffu,dun,o);
  }
  if(l==0){
    float cu=fminf(fmaxf(dzu*5.f,-5.f),5.f);
    float ci=fminf(fmaxf(dzi*5.f,-5.f),5.f);
    float diff=dup-dun;
    float bpr=fmaxf(-diff,0.f)+log1pf(expf(-fabsf(diff)));
    atomicAdd(&g_acc[3],(double)(cu+ci));
    atomicAdd(&g_acc[2],(double)bpr);
  }
}

// per-b: sum_j exp(dot(Z[ids[b]], X[j])/T); log2(e)/T folded into G.
__global__ void k_negsum(const int* __restrict__ ids, const float* __restrict__ Z,
                         const float* __restrict__ X, int N, int isItem){
  __shared__ float Gs[64][65];
  __shared__ float Xs[64][65];
  __shared__ float Ps[64][17];
  int b0=blockIdx.y*64;
  int j0=blockIdx.x*64;
  int tx=threadIdx.x, ty=threadIdx.y;
  int tid=ty*16+tx;
  const float scale=7.213475204444817f; // log2(e)/0.2
  for(int idx=tid; idx<64*64; idx+=256){
    int r=idx>>6, c=idx&63;
    Gs[r][c]=Z[ids[b0+r]*64+c]*scale;
    int j=j0+r;
    Xs[r][c]=(j<N)? X[j*64+c] : 0.f;
  }
  __syncthreads();
  float acc[4][4];
  #pragma unroll
  for(int i=0;i<4;i++)
    #pragma unroll
    for(int j=0;j<4;j++) acc[i][j]=0.f;
  #pragma unroll 8
  for(int k=0;k<64;k++){
    float g[4], x[4];
    #pragma unroll
    for(int i=0;i<4;i++){ g[i]=Gs[ty+16*i][k]; x[i]=Xs[tx+16*i][k]; }
    #pragma unroll
    for(int i=0;i<4;i++)
      #pragma unroll
      for(int j=0;j<4;j++) acc[i][j] += g[i]*x[j];
  }
  #pragma unroll
  for(int i=0;i<4;i++){
    float s=0.f;
    #pragma unroll
    for(int j=0;j<4;j++){
      int jj=j0+tx+16*j;
      if(jj<N) s+=exp2f(acc[i][j]);
    }
    Ps[ty+16*i][tx]=s;
  }
  __syncthreads();
  if(tid<64){
    float s=0.f;
    #pragma unroll
    for(int t=0;t<16;t++) s+=Ps[tid][t];
    atomicAdd(&g_negS[isItem*BB + b0 + tid],(double)s);
  }
}

__global__ void k_final(float* __restrict__ out){
  __shared__ double sh[1024];
  int t=threadIdx.x;
  sh[t]=log(g_negS[t]+1e-8)+log(g_negS[BB+t]+1e-8);
  __syncthreads();
  for(int o=512;o;o>>=1){ if(t<o) sh[t]+=sh[t+o]; __syncthreads(); }
  if(t==0){
    double neg=sh[0]/(double)BB;
    double pos=g_acc[3]/(double)BB;
    double cl=-pos+neg;
    double bpr=g_acc[2]/(double)BB;
    double pr=0.01*(g_acc[0]/(double)NE);
    double reg=1e-5*g_acc[1];
    out[0]=(float)(bpr+0.2*cl+pr+reg);
    out[1]=(float)bpr;
    out[2]=(float)(0.2*cl);
    out[3]=(float)pr;
  }
}

#define GA(p,s) do{ void* t_=0; cudaGetSymbolAddress(&t_,s); p=(decltype(p))t_; }while(0)

extern "C" void kernel_launch(void* const* d_in, const int* in_sizes, int n_in,
                              void* d_out, int out_size){
  const float* E_u_0 =(const float*)d_in[0];
  const float* E_i_0 =(const float*)d_in[1];
  const float* fuse_w=(const float*)d_in[2];
  const float* fuse_b=(const float*)d_in[3];
  const float* W1u   =(const float*)d_in[4];
  const float* W1i   =(const float*)d_in[5];
  const float* b1    =(const float*)d_in[6];
  const float* W2    =(const float*)d_in[7];
  const float* b2    =(const float*)d_in[8];
  const float* att_a =(const float*)d_in[9];
  const float* wv    =(const float*)d_in[10];
  const float* Wg    =(const float*)d_in[11];
  const float* adj   =(const float*)d_in[12];
  const float* dm    =(const float*)d_in[13];
  const float* da    =(const float*)d_in[14];
  const int* esrc=(const int*)d_in[15];
  const int* edst=(const int*)d_in[16];
  const int* uids=(const int*)d_in[17];
  const int* iids=(const int*)d_in[18];
  const int* pos =(const int*)d_in[19];
  const int* neg =(const int*)d_in[20];
  float* out=(float*)d_out;

  float *Eu1,*Eu2,*EuS,*U1,*Hg,*hu,*Zu,*Ei1,*Ei2,*EiS,*I1,*hi,*Zi,*au,*ai,*aug;
  int *rpu,*rpi,*cu,*ci,*du,*di,*colu,*eidu,*coli,*eidi;
  GA(Eu1,g_Eu1); GA(Eu2,g_Eu2); GA(EuS,g_EuS); GA(U1,g_U1); GA(Hg,g_Hg);
  GA(hu,g_hu); GA(Zu,g_Zu); GA(Ei1,g_Ei1); GA(Ei2,g_Ei2); GA(EiS,g_EiS);
  GA(I1,g_I1); GA(hi,g_hi); GA(Zi,g_Zi); GA(au,g_au); GA(ai,g_ai); GA(aug,g_aug);
  GA(rpu,g_rowptr_u); GA(rpi,g_rowptr_i); GA(cu,g_cur_u); GA(ci,g_cur_i);
  GA(du,g_deg_u); GA(di,g_deg_i); GA(colu,g_col_u); GA(eidu,g_eid_u);
  GA(coli,g_col_i); GA(eidi,g_eid_i);

  dim3 b256(256), bsp(64,4);
  int gU=(NU+3)/4, gI=(NI+3)/4;

  k_init<<<391,b256>>>();
  k_count<<<(NE+255)/256,b256>>>(esrc,edst);
  k_scan<<<1,1024>>>(du,rpu,cu,NU);
  k_scan<<<1,1024>>>(di,rpi,ci,NI);
  k_fill<<<(NE+255)/256,b256>>>(esrc,edst);

  // node-side precomputes for views
  k_gemm_node<<<gU,bsp>>>(E_u_0,W1u,b1,U1,NU);
  k_gemm_node<<<gI,bsp>>>(E_i_0,W1i,0,I1,NI);
  k_att<<<(NU*32+255)/256,b256>>>(E_u_0,att_a,au,NU);
  k_att<<<(NI*32+255)/256,b256>>>(E_i_0,att_a+64,ai,NI);

  // main propagation (2 layers)
  k_spmm<<<gU,bsp>>>(rpu,colu,eidu,adj,dm+0*NE,E_i_0,Eu1,NU);
  k_spmm<<<gI,bsp>>>(rpi,coli,eidi,adj,dm+1*NE,E_u_0,Ei1,NI);
  k_spmm<<<gU,bsp>>>(rpu,colu,eidu,adj,dm+2*NE,Ei1,Eu2,NU);
  k_spmm<<<gI,bsp>>>(rpi,coli,eidi,adj,dm+3*NE,Eu1,Ei2,NI);
  k_combine<<<(NU*64+255)/256,b256>>>(E_u_0,Eu1,Eu2,EuS,NU*64);
  k_combine<<<(NI*64+255)/256,b256>>>(E_i_0,Ei1,Ei2,EiS,NI*64);

  // GCN view: one clean propagation on (EuS, EiS)
  k_spmm<<<gU,bsp>>>(rpu,colu,eidu,adj,0,EiS,hu,NU);
  k_spmm<<<gI,bsp>>>(rpi,coli,eidi,adj,0,EuS,hi,NI);
  k_gemm_node<<<gU,bsp>>>(hu,Wg,0,Hg,NU);

  // edge passes
  k_edge1<<<(NE*32+255)/256,b256>>>(esrc,edst,W2,b2,wv,fuse_w,fuse_b);
  k_edge2<<<(NE+255)/256,b256>>>(fuse_w,fuse_b,adj);

  // augmented propagation (reuse layer buffers)
  k_spmm<<<gU,bsp>>>(rpu,colu,eidu,aug,da+0*NE,E_i_0,Eu1,NU);
  k_spmm<<<gI,bsp>>>(rpi,coli,eidi,aug,da+1*NE,E_u_0,Ei1,NI);
  k_spmm<<<gU,bsp>>>(rpu,colu,eidu,aug,da+2*NE,Ei1,Eu2,NU);
  k_spmm<<<gI,bsp>>>(rpi,coli,eidi,aug,da+3*NE,Eu1,Ei2,NI);
  k_combine<<<(NU*64+255)/256,b256>>>(E_u_0,Eu1,Eu2,Zu,NU*64);
  k_combine<<<(NI*64+255)/256,b256>>>(E_i_0,Ei1,Ei2,Zi,NI*64);

  // regularization
  k_sqsum<<<512,b256>>>(E_u_0,NU*64);
  k_sqsum<<<512,b256>>>(E_i_0,NI*64);
  k_sqsum<<<256,b256>>>(fuse_w,NE);
  k_sqsum<<<256,b256>>>(fuse_b,NE);
  k_sqsum<<<4,b256>>>(W1u,4096);
  k_sqsum<<<4,b256>>>(W1i,4096);
  k_sqsum<<<1,b256>>>(b1,64);
  k_sqsum<<<1,b256>>>(W2,64);
  k_sqsum<<<1,b256>>>(b2,1);
  k_sqsum<<<1,b256>>>(att_a,128);
  k_sqsum<<<256,b256>>>(wv,NE);
  k_sqsum<<<4,b256>>>(Wg,4096);

  // batch losses
  k_small<<<(BB*32+255)/256,b256>>>(uids,iids,pos,neg);
  dim3 bn(16,16);
  k_negsum<<<dim3((NU+63)/64,BB/64),bn>>>(uids,Zu,EuS,NU,0);
  k_negsum<<<dim3((NI+63)/64,BB/64),bn>>>(iids,Zi,EiS,NI,1);

  k_final<<<1,1024>>>(out);
}

// round 3
// speedup vs baseline: 1.5049x; 1.5049x over previous
#include <cuda_runtime.h>
#include <math.h>

#define NU 100000
#define NI 50000
#define NE 800000
#define BB 1024
typedef unsigned long long ull;

__device__ float g_Eu1[NU*64];
__device__ float g_EuS[NU*64];
__device__ float g_U1 [NU*64];
__device__ float g_Hg [NU*64];
__device__ float g_hu [NU*64];
__device__ float g_Zu [NU*64];
__device__ float g_Ei1[NI*64];
__device__ float g_EiS[NI*64];
__device__ float g_I1 [NI*64];
__device__ float g_hi [NI*64];
__device__ float g_Zi [NI*64];
__device__ float g_au[NU];
__device__ float g_ai[NI];
__device__ float g_views[4*NE];
__device__ float g_pre[NE];
__device__ float g_aug[NE];
__device__ int   g_rowptr_u[NU+1];
__device__ int   g_rowptr_i[NI+1];
__device__ int   g_cur_u[NU];
__device__ int   g_cur_i[NI];
__device__ int   g_deg_u[NU];
__device__ int   g_deg_i[NI];
__device__ int   g_part_u[512];
__device__ int   g_part_i[512];
__device__ int   g_col_u[NE];
__device__ int   g_eid_u[NE];
__device__ int   g_col_i[NE];
__device__ int   g_eid_i[NE];
__device__ double g_expsum[4];
__device__ double g_acc[4];     // 0: pr, 1: reg, 2: bpr, 3: pos
__device__ double g_negS[2*BB];

__device__ __forceinline__ float sigf(float x){ return 1.f/(1.f+expf(-x)); }

__device__ __forceinline__ ull fma2(ull a, ull b, ull c){
  ull d;
  asm("fma.rn.f32x2 %0, %1, %2, %3;" : "=l"(d) : "l"(a), "l"(b), "l"(c));
  return d;
}

__global__ void k_init(){
  int i=blockIdx.x*blockDim.x+threadIdx.x, st=gridDim.x*blockDim.x;
  for(int t=i;t<NU;t+=st) g_deg_u[t]=0;
  for(int t=i;t<NI;t+=st) g_deg_i[t]=0;
  for(int t=i;t<2*BB;t+=st) g_negS[t]=0.0;
  if(i<4){ g_expsum[i]=0.0; g_acc[i]=0.0; }
}

__global__ void k_count(const int* __restrict__ src, const int* __restrict__ dst){
  int e=blockIdx.x*blockDim.x+threadIdx.x;
  if(e<NE){ atomicAdd(&g_deg_u[src[e]],1); atomicAdd(&g_deg_i[dst[e]],1); }
}

// ---- hierarchical exclusive scan of deg -> rowptr, cur ----
__global__ void k_scanA(const int* __restrict__ deg, int n, int* __restrict__ part){
  __shared__ int sh[256];
  int i=blockIdx.x*256+threadIdx.x;
  sh[threadIdx.x]=(i<n)?deg[i]:0;
  __syncthreads();
  for(int o=128;o;o>>=1){ if(threadIdx.x<o) sh[threadIdx.x]+=sh[threadIdx.x+o]; __syncthreads(); }
  if(threadIdx.x==0) part[blockIdx.x]=sh[0];
}
__global__ void k_scanB(int* __restrict__ part, int nb){
  __shared__ int sh[512];
  int t=threadIdx.x;
  int v=(t<nb)?part[t]:0;
  sh[t]=v; __syncthreads();
  for(int o=1;o<512;o<<=1){ int a=(t>=o)?sh[t-o]:0; __syncthreads(); sh[t]+=a; __syncthreads(); }
  if(t<nb) part[t]=sh[t]-v;
}
__global__ void k_scanC(const int* __restrict__ deg, int n, const int* __restrict__ part,
                        int* __restrict__ rowptr, int* __restrict__ cur){
  __shared__ int sh[256];
  int i=blockIdx.x*256+threadIdx.x;
  int v=(i<n)?deg[i]:0;
  sh[threadIdx.x]=v; __syncthreads();
  for(int o=1;o<256;o<<=1){ int a=(threadIdx.x>=o)?sh[threadIdx.x-o]:0; __syncthreads(); sh[threadIdx.x]+=a; __syncthreads(); }
  int excl=part[blockIdx.x]+sh[threadIdx.x]-v;
  if(i<n){ rowptr[i]=excl; cur[i]=excl; }
  if(i==n-1) rowptr[n]=excl+v;
}

__global__ void k_fill(const int* __restrict__ src, const int* __restrict__ dst){
  int e=blockIdx.x*blockDim.x+threadIdx.x;
  if(e<NE){
    int s=src[e], d=dst[e];
    int p=atomicAdd(&g_cur_u[s],1); g_col_u[p]=d; g_eid_u[p]=e;
    int q=atomicAdd(&g_cur_i[d],1); g_col_i[q]=s; g_eid_i[q]=e;
  }
}

// Y[r,:] = (A?A[r,:]:0)+(B?B[r,:]:0)+ sum_j w_j * X[col_j,:]
// 256 threads = 8 warps, 2 rows/warp, 16 lanes/row, float4 per lane.
__global__ void k_spmm(const int* __restrict__ rowptr, const int* __restrict__ col,
                       const int* __restrict__ eid, const float* __restrict__ vals,
                       const float* __restrict__ drop, const float* __restrict__ X,
                       const float* __restrict__ A, const float* __restrict__ Bv,
                       float* __restrict__ Y, int nrows){
  int tid=threadIdx.x;
  int warp=tid>>5, lane=tid&31;
  int half=lane>>4, sub=lane&15;
  int r=blockIdx.x*16 + warp*2 + half;
  int beg=0,end=0;
  if(r<nrows){ beg=rowptr[r]; end=rowptr[r+1]; }
  int deg=end-beg;
  int degO=__shfl_xor_sync(0xffffffffu,deg,16);
  int maxdeg=max(deg,degO);
  float4 acc=make_float4(0.f,0.f,0.f,0.f);
  for(int base=0; base<maxdeg; base+=16){
    int c=0; float v=0.f;
    if(base+sub<deg){
      int j=beg+base+sub;
      int id=eid[j];
      v=vals[id];
      if(drop) v=(drop[id]>0.25f)? v*1.3333333333333333f : 0.f;
      c=col[j];
    }
    #pragma unroll 4
    for(int q=0;q<16;q++){
      float vq=__shfl_sync(0xffffffffu,v,q,16);
      int   cq=__shfl_sync(0xffffffffu,c,q,16);
      if(vq!=0.f){
        float4 x=*(const float4*)&X[cq*64+sub*4];
        acc.x+=vq*x.x; acc.y+=vq*x.y; acc.z+=vq*x.z; acc.w+=vq*x.w;
      }
    }
  }
  if(r<nrows){
    int o=r*64+sub*4;
    if(A){ float4 a=*(const float4*)&A[o]; acc.x+=a.x; acc.y+=a.y; acc.z+=a.z; acc.w+=a.w; }
    if(Bv){ float4 b=*(const float4*)&Bv[o]; acc.x+=b.x; acc.y+=b.y; acc.z+=b.z; acc.w+=b.w; }
    *(float4*)&Y[o]=acc;
  }
}

// Y = X @ W (+bias), [n,64]@[64,64]; block (16,16), 16 rows/block, float4 cols
__global__ void k_gemm_node(const float* __restrict__ X, const float* __restrict__ W,
                            const float* __restrict__ bias, float* __restrict__ Y, int n){
  __shared__ float Ws[64*64];
  __shared__ float Xs[16][64];
  int tx=threadIdx.x, ty=threadIdx.y;
  int tid=ty*16+tx;
  for(int t=tid;t<4096;t+=256) Ws[t]=W[t];
  int r=blockIdx.x*16+ty;
  if(r<n) ((float4*)Xs[ty])[tx]=((const float4*)&X[r*64])[tx];
  __syncthreads();
  if(r<n){
    float4 acc = bias ? ((const float4*)bias)[tx] : make_float4(0.f,0.f,0.f,0.f);
    #pragma unroll
    for(int k=0;k<64;k++){
      float xv=Xs[ty][k];
      float4 w=((const float4*)&Ws[k*64])[tx];
      acc.x+=xv*w.x; acc.y+=xv*w.y; acc.z+=xv*w.z; acc.w+=xv*w.w;
    }
    ((float4*)&Y[r*64])[tx]=acc;
  }
}

__global__ void k_att(const float* __restrict__ X, const float* __restrict__ a,
                      float* __restrict__ out, int n){
  int w=(blockIdx.x*blockDim.x+threadIdx.x)>>5;
  int l=threadIdx.x&31;
  if(w>=n) return;
  float s = X[w*64+l]*a[l] + X[w*64+l+32]*a[l+32];
  #pragma unroll
  for(int o=16;o;o>>=1) s += __shfl_xor_sync(0xffffffffu,s,o);
  if(l==0) out[w]=s;
}

// 8 lanes per edge, float4 loads
__global__ void k_edge1(const int* __restrict__ src, const int* __restrict__ dst,
                        const float* __restrict__ W2, const float* __restrict__ b2,
                        const float* __restrict__ wv, const float* __restrict__ fw,
                        const float* __restrict__ fb){
  __shared__ float4 W2s[16];
  __shared__ double sacc[4];
  int tid=threadIdx.x;
  if(tid<16) W2s[tid]=((const float4*)W2)[tid];
  if(tid<4)  sacc[tid]=0.0;
  __syncthreads();
  int gt=blockIdx.x*blockDim.x+tid;
  int e=gt>>3, l=gt&7;
  float m=0.f,gc=0.f,pr=0.f;
  int s=0,t=0;
  if(e<NE){
    s=src[e]; t=dst[e];
    const float4* U1p=(const float4*)&g_U1[s*64];
    const float4* I1p=(const float4*)&g_I1[t*64];
    const float4* Hgp=(const float4*)&g_Hg[s*64];
    const float4* hip=(const float4*)&g_hi[t*64];
    const float4* Sup=(const float4*)&g_EuS[s*64];
    const float4* Sip=(const float4*)&g_EiS[t*64];
    #pragma unroll
    for(int h=0;h<2;h++){
      int idx=l+8*h;
      float4 u=U1p[idx], i4=I1p[idx], w2=W2s[idx];
      m += fmaxf(u.x+i4.x,0.f)*w2.x + fmaxf(u.y+i4.y,0.f)*w2.y
         + fmaxf(u.z+i4.z,0.f)*w2.z + fmaxf(u.w+i4.w,0.f)*w2.w;
      float4 hg=Hgp[idx], hh=hip[idx];
      gc += hg.x*hh.x+hg.y*hh.y+hg.z*hh.z+hg.w*hh.w;
      float4 su=Sup[idx], si=Sip[idx];
      pr += su.x*si.x+su.y*si.y+su.z*si.z+su.w*si.w;
    }
  }
  #pragma unroll
  for(int o=4;o;o>>=1){
    m +=__shfl_xor_sync(0xffffffffu,m,o,8);
    gc+=__shfl_xor_sync(0xffffffffu,gc,o,8);
    pr+=__shfl_xor_sync(0xffffffffu,pr,o,8);
  }
  if(e<NE && l==0){
    float v0=sigf(m+b2[0]);
    float v1=sigf(wv[e]);
    float v2=sigf(gc);
    float a=g_au[s]+g_ai[t];
    float v3=sigf(a>0.f? a : 0.2f*a);
    g_views[e]=v0; g_views[NE+e]=v1; g_views[2*NE+e]=v2; g_views[3*NE+e]=v3;
    g_pre[e]=sigf(pr);
    float w=fw[e], b=fb[e];
    atomicAdd(&sacc[0],(double)expf(tanhf(w*v0+b)));
    atomicAdd(&sacc[1],(double)expf(tanhf(w*v1+b)));
    atomicAdd(&sacc[2],(double)expf(tanhf(w*v2+b)));
    atomicAdd(&sacc[3],(double)expf(tanhf(w*v3+b)));
  }
  __syncthreads();
  if(tid<4) atomicAdd(&g_expsum[tid],sacc[tid]);
}

__global__ void k_edge2(const float* __restrict__ fw, const float* __restrict__ fb,
                        const float* __restrict__ adj){
  int e=blockIdx.x*blockDim.x+threadIdx.x;
  float lp=0.f;
  if(e<NE){
    float S0=(float)g_expsum[0], S1=(float)g_expsum[1];
    float S2=(float)g_expsum[2], S3=(float)g_expsum[3];
    float w=fw[e], b=fb[e];
    float v0=g_views[e], v1=g_views[NE+e], v2=g_views[2*NE+e], v3=g_views[3*NE+e];
    float Ag = expf(tanhf(w*v0+b))/S0*v0
             + expf(tanhf(w*v1+b))/S1*v1
             + expf(tanhf(w*v2+b))/S2*v2
             + expf(tanhf(w*v3+b))/S3*v3;
    float sumv=v0+v1+v2+v3;
    float baew=g_pre[e]*((sumv-3.f*Ag)*0.2f);
    g_aug[e]=baew*adj[e];
    lp=-logf(baew);
  }
  #pragma unroll
  for(int o=16;o;o>>=1) lp += __shfl_xor_sync(0xffffffffu,lp,o);
  if((threadIdx.x&31)==0) atomicAdd(&g_acc[0],(double)lp);
}

__global__ void k_sqsum(const float* __restrict__ p, int n){
  double s=0.0;
  for(int i=blockIdx.x*blockDim.x+threadIdx.x;i<n;i+=gridDim.x*blockDim.x){
    float v=p[i]; s+=(double)v*(double)v;
  }
  #pragma unroll
  for(int o=16;o;o>>=1) s += __shfl_xor_sync(0xffffffffu,s,o);
  if((threadIdx.x&31)==0) atomicAdd(&g_acc[1],s);
}

__global__ void k_sqsum3(const float* __restrict__ a, const float* __restrict__ b,
                         const float* __restrict__ c, int n){
  double s=0.0;
  for(int i=blockIdx.x*blockDim.x+threadIdx.x;i<n;i+=gridDim.x*blockDim.x){
    float x=a[i],y=b[i],z=c[i];
    s+=(double)x*x+(double)y*y+(double)z*z;
  }
  #pragma unroll
  for(int o=16;o;o>>=1) s += __shfl_xor_sync(0xffffffffu,s,o);
  if((threadIdx.x&31)==0) atomicAdd(&g_acc[1],s);
}

__global__ void k_small(const int* __restrict__ uids, const int* __restrict__ iids,
                        const int* __restrict__ pos, const int* __restrict__ neg){
  int w=(blockIdx.x*blockDim.x+threadIdx.x)>>5;
  int l=threadIdx.x&31;
  if(w>=BB) return;
  int u=uids[w], it=iids[w], p=pos[w], ng=neg[w];
  float dzu=0,dzi=0,dup=0,dun=0;
  #pragma unroll
  for(int d=l; d<64; d+=32){
    float eu=g_EuS[u*64+d];
    dzu += g_Zu[u*64+d]*eu;
    dzi += g_Zi[it*64+d]*g_EiS[it*64+d];
    dup += eu*g_EiS[p*64+d];
    dun += eu*g_EiS[ng*64+d];
  }
  #pragma unroll
  for(int o=16;o;o>>=1){
    dzu+=__shfl_xor_sync(0xffffffffu,dzu,o);
    dzi+=__shfl_xor_sync(0xffffffffu,dzi,o);
    dup+=__shfl_xor_sync(0xffffffffu,dup,o);
    dun+=__shfl_xor_sync(0xffffffffu,dun,o);
  }
  if(l==0){
    float cu=fminf(fmaxf(dzu*5.f,-5.f),5.f);
    float ci=fminf(fmaxf(dzi*5.f,-5.f),5.f);
    float diff=dup-dun;
    float bpr=fmaxf(-diff,0.f)+log1pf(expf(-fabsf(diff)));
    atomicAdd(&g_acc[3],(double)(cu+ci));
    atomicAdd(&g_acc[2],(double)bpr);
  }
}

// per-b: sum_j exp(dot(Z[ids[b]], X[j])/T); log2(e)/T folded into G; f32x2 FMA along k
__global__ void k_negsum(const int* __restrict__ ids, const float* __restrict__ Z,
                         const float* __restrict__ X, int N, int isItem){
  __shared__ float Gs[64][66];
  __shared__ float Xs[64][66];
  __shared__ float Ps[64][17];
  int b0=blockIdx.y*64, j0=blockIdx.x*64;
  int tx=threadIdx.x, ty=threadIdx.y;
  int tid=ty*16+tx;
  const float scale=7.213475204444817f; // log2(e)/0.2
  for(int idx=tid; idx<64*64; idx+=256){
    int r=idx>>6, c=idx&63;
    Gs[r][c]=Z[ids[b0+r]*64+c]*scale;
    int j=j0+r;
    Xs[r][c]=(j<N)? X[j*64+c] : 0.f;
  }
  __syncthreads();
  ull acc2[4][4];
  #pragma unroll
  for(int i=0;i<4;i++)
    #pragma unroll
    for(int j=0;j<4;j++) acc2[i][j]=0ull;
  const ull* Gp[4]; const ull* Xp[4];
  #pragma unroll
  for(int i=0;i<4;i++){ Gp[i]=(const ull*)&Gs[ty+16*i][0]; Xp[i]=(const ull*)&Xs[tx+16*i][0]; }
  #pragma unroll 8
  for(int k2=0;k2<32;k2++){
    ull g[4],x[4];
    #pragma unroll
    for(int i=0;i<4;i++){ g[i]=Gp[i][k2]; x[i]=Xp[i][k2]; }
    #pragma unroll
    for(int i=0;i<4;i++)
      #pragma unroll
      for(int j=0;j<4;j++) acc2[i][j]=fma2(g[i],x[j],acc2[i][j]);
  }
  #pragma unroll
  for(int i=0;i<4;i++){
    float s=0.f;
    #pragma unroll
    for(int j=0;j<4;j++){
      int jj=j0+tx+16*j;
      float lo=__uint_as_float((unsigned)(acc2[i][j]&0xffffffffull));
      float hi=__uint_as_float((unsigned)(acc2[i][j]>>32));
      if(jj<N) s+=exp2f(lo+hi);
    }
    Ps[ty+16*i][tx]=s;
  }
  __syncthreads();
  if(tid<64){
    float s=0.f;
    #pragma unroll
    for(int t=0;t<16;t++) s+=Ps[tid][t];
    atomicAdd(&g_negS[isItem*BB + b0 + tid],(double)s);
  }
}

__global__ void k_final(float* __restrict__ out){
  __shared__ double sh[1024];
  int t=threadIdx.x;
  sh[t]=log(g_negS[t]+1e-8)+log(g_negS[BB+t]+1e-8);
  __syncthreads();
  for(int o=512;o;o>>=1){ if(t<o) sh[t]+=sh[t+o]; __syncthreads(); }
  if(t==0){
    double neg=sh[0]/(double)BB;
    double pos=g_acc[3]/(double)BB;
    double cl=-pos+neg;
    double bpr=g_acc[2]/(double)BB;
    double pr=0.01*(g_acc[0]/(double)NE);
    double reg=1e-5*g_acc[1];
    out[0]=(float)(bpr+0.2*cl+pr+reg);
    out[1]=(float)bpr;
    out[2]=(float)(0.2*cl);
    out[3]=(float)pr;
  }
}

#define GA(p,s) do{ void* t_=0; cudaGetSymbolAddress(&t_,s); p=(decltype(p))t_; }while(0)

extern "C" void kernel_launch(void* const* d_in, const int* in_sizes, int n_in,
                              void* d_out, int out_size){
  const float* E_u_0 =(const float*)d_in[0];
  const float* E_i_0 =(const float*)d_in[1];
  const float* fuse_w=(const float*)d_in[2];
  const float* fuse_b=(const float*)d_in[3];
  const float* W1u   =(const float*)d_in[4];
  const float* W1i   =(const float*)d_in[5];
  const float* b1    =(const float*)d_in[6];
  const float* W2    =(const float*)d_in[7];
  const float* b2    =(const float*)d_in[8];
  const float* att_a =(const float*)d_in[9];
  const float* wv    =(const float*)d_in[10];
  const float* Wg    =(const float*)d_in[11];
  const float* adj   =(const float*)d_in[12];
  const float* dm    =(const float*)d_in[13];
  const float* da    =(const float*)d_in[14];
  const int* esrc=(const int*)d_in[15];
  const int* edst=(const int*)d_in[16];
  const int* uids=(const int*)d_in[17];
  const int* iids=(const int*)d_in[18];
  const int* pos =(const int*)d_in[19];
  const int* neg =(const int*)d_in[20];
  float* out=(float*)d_out;

  float *Eu1,*EuS,*U1,*Hg,*hu,*Zu,*Ei1,*EiS,*I1,*hi,*Zi,*au,*ai,*aug;
  int *rpu,*rpi,*cu,*ci,*du,*di,*pu,*pi,*colu,*eidu,*coli,*eidi;
  GA(Eu1,g_Eu1); GA(EuS,g_EuS); GA(U1,g_U1); GA(Hg,g_Hg);
  GA(hu,g_hu); GA(Zu,g_Zu); GA(Ei1,g_Ei1); GA(EiS,g_EiS);
  GA(I1,g_I1); GA(hi,g_hi); GA(Zi,g_Zi); GA(au,g_au); GA(ai,g_ai); GA(aug,g_aug);
  GA(rpu,g_rowptr_u); GA(rpi,g_rowptr_i); GA(cu,g_cur_u); GA(ci,g_cur_i);
  GA(du,g_deg_u); GA(di,g_deg_i); GA(pu,g_part_u); GA(pi,g_part_i);
  GA(colu,g_col_u); GA(eidu,g_eid_u); GA(coli,g_col_i); GA(eidi,g_eid_i);

  dim3 b256(256), bg(16,16);
  int gU=(NU+15)/16, gI=(NI+15)/16;
  int nbU=(NU+255)/256, nbI=(NI+255)/256;

  k_init<<<391,b256>>>();
  k_count<<<(NE+255)/256,b256>>>(esrc,edst);
  k_scanA<<<nbU,b256>>>(du,NU,pu);
  k_scanA<<<nbI,b256>>>(di,NI,pi);
  k_scanB<<<1,512>>>(pu,nbU);
  k_scanB<<<1,512>>>(pi,nbI);
  k_scanC<<<nbU,b256>>>(du,NU,pu,rpu,cu);
  k_scanC<<<nbI,b256>>>(di,NI,pi,rpi,ci);
  k_fill<<<(NE+255)/256,b256>>>(esrc,edst);

  // node-side precomputes for views
  k_gemm_node<<<gU,bg>>>(E_u_0,W1u,b1,U1,NU);
  k_gemm_node<<<gI,bg>>>(E_i_0,W1i,0,I1,NI);
  k_att<<<(NU*32+255)/256,b256>>>(E_u_0,att_a,au,NU);
  k_att<<<(NI*32+255)/256,b256>>>(E_i_0,att_a+64,ai,NI);

  // main propagation (2 layers), layer-2 fused with sum
  k_spmm<<<gU,b256>>>(rpu,colu,eidu,adj,dm+0*NE,E_i_0,0,0,Eu1,NU);
  k_spmm<<<gI,b256>>>(rpi,coli,eidi,adj,dm+1*NE,E_u_0,0,0,Ei1,NI);
  k_spmm<<<gU,b256>>>(rpu,colu,eidu,adj,dm+2*NE,Ei1,E_u_0,Eu1,EuS,NU);
  k_spmm<<<gI,b256>>>(rpi,coli,eidi,adj,dm+3*NE,Eu1,E_i_0,Ei1,EiS,NI);

  // GCN view: one clean propagation on (EuS, EiS)
  k_spmm<<<gU,b256>>>(rpu,colu,eidu,adj,0,EiS,0,0,hu,NU);
  k_spmm<<<gI,b256>>>(rpi,coli,eidi,adj,0,EuS,0,0,hi,NI);
  k_gemm_node<<<gU,bg>>>(hu,Wg,0,Hg,NU);

  // edge passes
  k_edge1<<<(NE*8+255)/256,b256>>>(esrc,edst,W2,b2,wv,fuse_w,fuse_b);
  k_edge2<<<(NE+255)/256,b256>>>(fuse_w,fuse_b,adj);

  // augmented propagation
  k_spmm<<<gU,b256>>>(rpu,colu,eidu,aug,da+0*NE,E_i_0,0,0,Eu1,NU);
  k_spmm<<<gI,b256>>>(rpi,coli,eidi,aug,da+1*NE,E_u_0,0,0,Ei1,NI);
  k_spmm<<<gU,b256>>>(rpu,colu,eidu,aug,da+2*NE,Ei1,E_u_0,Eu1,Zu,NU);
  k_spmm<<<gI,b256>>>(rpi,coli,eidi,aug,da+3*NE,Eu1,E_i_0,Ei1,Zi,NI);

  // regularization
  k_sqsum<<<512,b256>>>(E_u_0,NU*64);
  k_sqsum<<<512,b256>>>(E_i_0,NI*64);
  k_sqsum3<<<512,b256>>>(fuse_w,fuse_b,wv,NE);
  k_sqsum<<<4,b256>>>(W1u,4096);
  k_sqsum<<<4,b256>>>(W1i,4096);
  k_sqsum<<<1,b256>>>(b1,64);
  k_sqsum<<<1,b256>>>(W2,64);
  k_sqsum<<<1,b256>>>(b2,1);
  k_sqsum<<<1,b256>>>(att_a,128);
  k_sqsum<<<4,b256>>>(Wg,4096);

  // batch losses
  k_small<<<(BB*32+255)/256,b256>>>(uids,iids,pos,neg);
  dim3 bn(16,16);
  k_negsum<<<dim3((NU+63)/64,BB/64),bn>>>(uids,Zu,EuS,NU,0);
  k_negsum<<<dim3((NI+63)/64,BB/64),bn>>>(iids,Zi,EiS,NI,1);

  k_final<<<1,1024>>>(out);
}

// round 4
// speedup vs baseline: 1.6552x; 1.0999x over previous
#include <cuda_runtime.h>
#include <math.h>

#define NU 100000
#define NI 50000
#define NE 800000
#define BB 1024
typedef unsigned long long ull;

__device__ float g_Eu1[NU*64];
__device__ float g_EuS[NU*64];
__device__ float g_U1 [NU*64];
__device__ float g_Hg [NU*64];
__device__ float g_hu [NU*64];
__device__ float g_Zu [NU*64];
__device__ float g_Ei1[NI*64];
__device__ float g_EiS[NI*64];
__device__ float g_I1 [NI*64];
__device__ float g_hi [NI*64];
__device__ float g_Zi [NI*64];
__device__ float g_au[NU];
__device__ float g_ai[NI];
__device__ float g_views[4*NE];
__device__ float g_pre[NE];
__device__ float g_aug[NE];
__device__ int   g_rowptr_u[NU+1];
__device__ int   g_rowptr_i[NI+1];
__device__ int   g_cur_u[NU];
__device__ int   g_cur_i[NI];
__device__ int   g_deg_u[NU];
__device__ int   g_deg_i[NI];
__device__ int   g_part_u[512];
__device__ int   g_part_i[512];
__device__ int   g_col_u[NE];
__device__ int   g_eid_u[NE];
__device__ int   g_col_i[NE];
__device__ int   g_eid_i[NE];
// CSR-ordered weight arrays
__device__ float g_wcu[NE],  g_wci[NE];    // clean adj
__device__ float g_wm0u[NE], g_wm1u[NE];   // main layer0/1, u-side
__device__ float g_wm0i[NE], g_wm1i[NE];   // main layer0/1, i-side
__device__ float g_wa0u[NE], g_wa1u[NE];   // aug layer0/1, u-side
__device__ float g_wa0i[NE], g_wa1i[NE];   // aug layer0/1, i-side
__device__ double g_expsum[4];
__device__ double g_acc[4];     // 0: pr, 1: reg, 2: bpr, 3: pos
__device__ double g_negS[2*BB];

__device__ __forceinline__ float sigf(float x){ return 1.f/(1.f+expf(-x)); }

__device__ __forceinline__ ull fma2(ull a, ull b, ull c){
  ull d;
  asm("fma.rn.f32x2 %0, %1, %2, %3;" : "=l"(d) : "l"(a), "l"(b), "l"(c));
  return d;
}

__global__ void k_init(){
  int i=blockIdx.x*blockDim.x+threadIdx.x, st=gridDim.x*blockDim.x;
  for(int t=i;t<NU;t+=st) g_deg_u[t]=0;
  for(int t=i;t<NI;t+=st) g_deg_i[t]=0;
  for(int t=i;t<2*BB;t+=st) g_negS[t]=0.0;
  if(i<4){ g_expsum[i]=0.0; g_acc[i]=0.0; }
}

__global__ void k_count(const int* __restrict__ src, const int* __restrict__ dst){
  int e=blockIdx.x*blockDim.x+threadIdx.x;
  if(e<NE){ atomicAdd(&g_deg_u[src[e]],1); atomicAdd(&g_deg_i[dst[e]],1); }
}

__global__ void k_scanA(const int* __restrict__ deg, int n, int* __restrict__ part){
  __shared__ int sh[256];
  int i=blockIdx.x*256+threadIdx.x;
  sh[threadIdx.x]=(i<n)?deg[i]:0;
  __syncthreads();
  for(int o=128;o;o>>=1){ if(threadIdx.x<o) sh[threadIdx.x]+=sh[threadIdx.x+o]; __syncthreads(); }
  if(threadIdx.x==0) part[blockIdx.x]=sh[0];
}
__global__ void k_scanB(int* __restrict__ part, int nb){
  __shared__ int sh[512];
  int t=threadIdx.x;
  int v=(t<nb)?part[t]:0;
  sh[t]=v; __syncthreads();
  for(int o=1;o<512;o<<=1){ int a=(t>=o)?sh[t-o]:0; __syncthreads(); sh[t]+=a; __syncthreads(); }
  if(t<nb) part[t]=sh[t]-v;
}
__global__ void k_scanC(const int* __restrict__ deg, int n, const int* __restrict__ part,
                        int* __restrict__ rowptr, int* __restrict__ cur){
  __shared__ int sh[256];
  int i=blockIdx.x*256+threadIdx.x;
  int v=(i<n)?deg[i]:0;
  sh[threadIdx.x]=v; __syncthreads();
  for(int o=1;o<256;o<<=1){ int a=(threadIdx.x>=o)?sh[threadIdx.x-o]:0; __syncthreads(); sh[threadIdx.x]+=a; __syncthreads(); }
  int excl=part[blockIdx.x]+sh[threadIdx.x]-v;
  if(i<n){ rowptr[i]=excl; cur[i]=excl; }
  if(i==n-1) rowptr[n]=excl+v;
}

__global__ void k_fill(const int* __restrict__ src, const int* __restrict__ dst){
  int e=blockIdx.x*blockDim.x+threadIdx.x;
  if(e<NE){
    int s=src[e], d=dst[e];
    int p=atomicAdd(&g_cur_u[s],1); g_col_u[p]=d; g_eid_u[p]=e;
    int q=atomicAdd(&g_cur_i[d],1); g_col_i[q]=s; g_eid_i[q]=e;
  }
}

// permute adj (+dropout-masked main weights) into CSR orders
__global__ void k_permw(const float* __restrict__ adj, const float* __restrict__ dm){
  int j=blockIdx.x*blockDim.x+threadIdx.x;
  const float R=1.3333333333333333f;
  if(j<NE){
    int id=g_eid_u[j]; float w=adj[id];
    g_wcu[j]=w;
    g_wm0u[j]=(dm[id]       >0.25f)? w*R:0.f;
    g_wm1u[j]=(dm[2*NE+id]  >0.25f)? w*R:0.f;
  } else if(j<2*NE){
    int jj=j-NE;
    int id=g_eid_i[jj]; float w=adj[id];
    g_wci[jj]=w;
    g_wm0i[jj]=(dm[NE+id]   >0.25f)? w*R:0.f;
    g_wm1i[jj]=(dm[3*NE+id] >0.25f)? w*R:0.f;
  }
}

__global__ void k_permaug(const float* __restrict__ da){
  int j=blockIdx.x*blockDim.x+threadIdx.x;
  const float R=1.3333333333333333f;
  if(j<NE){
    int id=g_eid_u[j]; float w=g_aug[id];
    g_wa0u[j]=(da[id]       >0.25f)? w*R:0.f;
    g_wa1u[j]=(da[2*NE+id]  >0.25f)? w*R:0.f;
  } else if(j<2*NE){
    int jj=j-NE;
    int id=g_eid_i[jj]; float w=g_aug[id];
    g_wa0i[jj]=(da[NE+id]   >0.25f)? w*R:0.f;
    g_wa1i[jj]=(da[3*NE+id] >0.25f)? w*R:0.f;
  }
}

// Y[r,:] = (A?A[r,:]:0)+(B?B[r,:]:0)+ sum_j w[j]*X[col[j],:]
// 256 thr = 8 warps, 2 rows/warp, 16 lanes/row, float4/lane, 4 accumulators.
__global__ void k_spmm(const int* __restrict__ rowptr, const int* __restrict__ col,
                       const float* __restrict__ w, const float* __restrict__ X,
                       const float* __restrict__ A, const float* __restrict__ Bv,
                       float* __restrict__ Y, int nrows){
  int tid=threadIdx.x;
  int warp=tid>>5, lane=tid&31;
  int half=lane>>4, sub=lane&15;
  int r=blockIdx.x*16 + warp*2 + half;
  int beg=0,end=0;
  if(r<nrows){ beg=rowptr[r]; end=rowptr[r+1]; }
  int deg=end-beg;
  int maxdeg=max(deg,__shfl_xor_sync(0xffffffffu,deg,16));
  float4 aa[4];
  #pragma unroll
  for(int q=0;q<4;q++) aa[q]=make_float4(0.f,0.f,0.f,0.f);
  for(int base=0; base<maxdeg; base+=16){
    int c=0; float v=0.f;
    if(base+sub<deg){
      int j=beg+base+sub;
      c=col[j]; v=w[j];
    }
    #pragma unroll
    for(int q=0;q<16;q++){
      float vq=__shfl_sync(0xffffffffu,v,q,16);
      int   cq=__shfl_sync(0xffffffffu,c,q,16);
      if(vq!=0.f){
        float4 x=*(const float4*)&X[cq*64+sub*4];
        aa[q&3].x+=vq*x.x; aa[q&3].y+=vq*x.y; aa[q&3].z+=vq*x.z; aa[q&3].w+=vq*x.w;
      }
    }
  }
  float4 acc;
  acc.x=(aa[0].x+aa[1].x)+(aa[2].x+aa[3].x);
  acc.y=(aa[0].y+aa[1].y)+(aa[2].y+aa[3].y);
  acc.z=(aa[0].z+aa[1].z)+(aa[2].z+aa[3].z);
  acc.w=(aa[0].w+aa[1].w)+(aa[2].w+aa[3].w);
  if(r<nrows){
    int o=r*64+sub*4;
    if(A){ float4 a=*(const float4*)&A[o]; acc.x+=a.x; acc.y+=a.y; acc.z+=a.z; acc.w+=a.w; }
    if(Bv){ float4 b=*(const float4*)&Bv[o]; acc.x+=b.x; acc.y+=b.y; acc.z+=b.z; acc.w+=b.w; }
    *(float4*)&Y[o]=acc;
  }
}

// Y = X @ W (+bias); optional fused att scalar out: attOut[r]=dot(X[r,:],att)
__global__ void k_gemm_node(const float* __restrict__ X, const float* __restrict__ W,
                            const float* __restrict__ bias, const float* __restrict__ att,
                            float* __restrict__ Y, float* __restrict__ attOut, int n){
  __shared__ float Ws[64*64];
  __shared__ float Xs[16][64];
  __shared__ float atts[64];
  int tx=threadIdx.x, ty=threadIdx.y;
  int tid=ty*16+tx;
  for(int t=tid;t<4096;t+=256) Ws[t]=W[t];
  if(att && tid<64) atts[tid]=att[tid];
  int r=blockIdx.x*16+ty;
  if(r<n) ((float4*)Xs[ty])[tx]=((const float4*)&X[r*64])[tx];
  __syncthreads();
  if(r<n){
    float4 acc = bias ? ((const float4*)bias)[tx] : make_float4(0.f,0.f,0.f,0.f);
    #pragma unroll
    for(int k=0;k<64;k++){
      float xv=Xs[ty][k];
      float4 w=((const float4*)&Ws[k*64])[tx];
      acc.x+=xv*w.x; acc.y+=xv*w.y; acc.z+=xv*w.z; acc.w+=xv*w.w;
    }
    ((float4*)&Y[r*64])[tx]=acc;
  }
  if(att){
    float p=0.f;
    if(r<n){
      #pragma unroll
      for(int d=0;d<4;d++) p+=Xs[ty][tx*4+d]*atts[tx*4+d];
    }
    #pragma unroll
    for(int o=8;o;o>>=1) p+=__shfl_xor_sync(0xffffffffu,p,o,16);
    if(r<n && tx==0) attOut[r]=p;
  }
}

// edge views, CSR-item order: warp per item row; item-side vectors in registers.
__global__ void k_edge1(const float* __restrict__ W2, const float* __restrict__ b2,
                        const float* __restrict__ wv, const float* __restrict__ fw,
                        const float* __restrict__ fb){
  __shared__ float W2s[64];
  __shared__ double sacc[4];
  int tid=threadIdx.x, lane=tid&31, warp=tid>>5;
  if(tid<64) W2s[tid]=W2[tid];
  if(tid<4)  sacc[tid]=0.0;
  __syncthreads();
  int r=blockIdx.x*8+warp;   // item row
  float e0=0.f,e1=0.f,e2=0.f,e3=0.f;
  if(r<NI){
    float b2v=b2[0];
    float w2a=W2s[lane*2], w2b=W2s[lane*2+1];
    float2 i1 =*(const float2*)&g_I1 [r*64+lane*2];
    float2 hi2=*(const float2*)&g_hi [r*64+lane*2];
    float2 si =*(const float2*)&g_EiS[r*64+lane*2];
    float aiv=g_ai[r];
    int beg=g_rowptr_i[r], end=g_rowptr_i[r+1];
    for(int j=beg;j<end;j++){
      int u=g_col_i[j];
      float2 u1=*(const float2*)&g_U1 [u*64+lane*2];
      float2 hg=*(const float2*)&g_Hg [u*64+lane*2];
      float2 su=*(const float2*)&g_EuS[u*64+lane*2];
      float m  = fmaxf(u1.x+i1.x,0.f)*w2a + fmaxf(u1.y+i1.y,0.f)*w2b;
      float gc = hg.x*hi2.x + hg.y*hi2.y;
      float pr = su.x*si.x + su.y*si.y;
      #pragma unroll
      for(int o=16;o;o>>=1){
        m +=__shfl_xor_sync(0xffffffffu,m,o);
        gc+=__shfl_xor_sync(0xffffffffu,gc,o);
        pr+=__shfl_xor_sync(0xffffffffu,pr,o);
      }
      if(lane==0){
        int e=g_eid_i[j];
        float v0=sigf(m+b2v);
        float v1=sigf(wv[e]);
        float v2=sigf(gc);
        float a=g_au[u]+aiv;
        float v3=sigf(a>0.f? a : 0.2f*a);
        g_views[e]=v0; g_views[NE+e]=v1; g_views[2*NE+e]=v2; g_views[3*NE+e]=v3;
        g_pre[e]=sigf(pr);
        float w=fw[e], b=fb[e];
        e0+=expf(tanhf(w*v0+b));
        e1+=expf(tanhf(w*v1+b));
        e2+=expf(tanhf(w*v2+b));
        e3+=expf(tanhf(w*v3+b));
      }
    }
  }
  if(lane==0 && r<NI){
    atomicAdd(&sacc[0],(double)e0);
    atomicAdd(&sacc[1],(double)e1);
    atomicAdd(&sacc[2],(double)e2);
    atomicAdd(&sacc[3],(double)e3);
  }
  __syncthreads();
  if(tid<4) atomicAdd(&g_expsum[tid],sacc[tid]);
}

__global__ void k_edge2(const float* __restrict__ fw, const float* __restrict__ fb,
                        const float* __restrict__ adj){
  int e=blockIdx.x*blockDim.x+threadIdx.x;
  float lp=0.f;
  if(e<NE){
    float S0=(float)g_expsum[0], S1=(float)g_expsum[1];
    float S2=(float)g_expsum[2], S3=(float)g_expsum[3];
    float w=fw[e], b=fb[e];
    float v0=g_views[e], v1=g_views[NE+e], v2=g_views[2*NE+e], v3=g_views[3*NE+e];
    float Ag = expf(tanhf(w*v0+b))/S0*v0
             + expf(tanhf(w*v1+b))/S1*v1
             + expf(tanhf(w*v2+b))/S2*v2
             + expf(tanhf(w*v3+b))/S3*v3;
    float sumv=v0+v1+v2+v3;
    float baew=g_pre[e]*((sumv-3.f*Ag)*0.2f);
    g_aug[e]=baew*adj[e];
    lp=-logf(baew);
  }
  #pragma unroll
  for(int o=16;o;o>>=1) lp += __shfl_xor_sync(0xffffffffu,lp,o);
  if((threadIdx.x&31)==0) atomicAdd(&g_acc[0],(double)lp);
}

__global__ void k_sqsum(const float* __restrict__ p, int n){
  double s=0.0;
  for(int i=blockIdx.x*blockDim.x+threadIdx.x;i<n;i+=gridDim.x*blockDim.x){
    float v=p[i]; s+=(double)v*(double)v;
  }
  #pragma unroll
  for(int o=16;o;o>>=1) s += __shfl_xor_sync(0xffffffffu,s,o);
  if((threadIdx.x&31)==0) atomicAdd(&g_acc[1],s);
}

__global__ void k_sqsum3(const float* __restrict__ a, const float* __restrict__ b,
                         const float* __restrict__ c, int n){
  double s=0.0;
  for(int i=blockIdx.x*blockDim.x+threadIdx.x;i<n;i+=gridDim.x*blockDim.x){
    float x=a[i],y=b[i],z=c[i];
    s+=(double)x*x+(double)y*y+(double)z*z;
  }
  #pragma unroll
  for(int o=16;o;o>>=1) s += __shfl_xor_sync(0xffffffffu,s,o);
  if((threadIdx.x&31)==0) atomicAdd(&g_acc[1],s);
}

// all the small params in one launch
__global__ void k_sqsum_small(const float* __restrict__ W1u, const float* __restrict__ W1i,
                              const float* __restrict__ b1, const float* __restrict__ W2,
                              const float* __restrict__ b2, const float* __restrict__ att_a,
                              const float* __restrict__ Wg){
  const float* ps[7]={W1u,W1i,b1,W2,b2,att_a,Wg};
  const int    ln[7]={4096,4096,64,64,1,128,4096};
  double s=0.0;
  int i0=blockIdx.x*blockDim.x+threadIdx.x, st=gridDim.x*blockDim.x;
  for(int a=0;a<7;a++){
    const float* p=ps[a];
    for(int i=i0;i<ln[a];i+=st){ float v=p[i]; s+=(double)v*(double)v; }
  }
  #pragma unroll
  for(int o=16;o;o>>=1) s += __shfl_xor_sync(0xffffffffu,s,o);
  if((threadIdx.x&31)==0) atomicAdd(&g_acc[1],s);
}

__global__ void k_small(const int* __restrict__ uids, const int* __restrict__ iids,
                        const int* __restrict__ pos, const int* __restrict__ neg){
  int w=(blockIdx.x*blockDim.x+threadIdx.x)>>5;
  int l=threadIdx.x&31;
  if(w>=BB) return;
  int u=uids[w], it=iids[w], p=pos[w], ng=neg[w];
  float dzu=0,dzi=0,dup=0,dun=0;
  #pragma unroll
  for(int d=l; d<64; d+=32){
    float eu=g_EuS[u*64+d];
    dzu += g_Zu[u*64+d]*eu;
    dzi += g_Zi[it*64+d]*g_EiS[it*64+d];
    dup += eu*g_EiS[p*64+d];
    dun += eu*g_EiS[ng*64+d];
  }
  #pragma unroll
  for(int o=16;o;o>>=1){
    dzu+=__shfl_xor_sync(0xffffffffu,dzu,o);
    dzi+=__shfl_xor_sync(0xffffffffu,dzi,o);
    dup+=__shfl_xor_sync(0xffffffffu,dup,o);
    dun+=__shfl_xor_sync(0xffffffffu,dun,o);
  }
  if(l==0){
    float cu=fminf(fmaxf(dzu*5.f,-5.f),5.f);
    float ci=fminf(fmaxf(dzi*5.f,-5.f),5.f);
    float diff=dup-dun;
    float bpr=fmaxf(-diff,0.f)+log1pf(expf(-fabsf(diff)));
    atomicAdd(&g_acc[3],(double)(cu+ci));
    atomicAdd(&g_acc[2],(double)bpr);
  }
}

// per-b: sum_j exp(dot(Z[ids[b]], X[j])/T); log2(e)/T folded into G; f32x2 FMA
__global__ void k_negsum(const int* __restrict__ ids, const float* __restrict__ Z,
                         const float* __restrict__ X, int N, int isItem){
  __shared__ float Gs[64][66];
  __shared__ float Xs[64][66];
  __shared__ float Ps[64][17];
  int b0=blockIdx.y*64, j0=blockIdx.x*64;
  int tx=threadIdx.x, ty=threadIdx.y;
  int tid=ty*16+tx;
  const float scale=7.213475204444817f; // log2(e)/0.2
  for(int idx=tid; idx<64*64; idx+=256){
    int r=idx>>6, c=idx&63;
    Gs[r][c]=Z[ids[b0+r]*64+c]*scale;
    int j=j0+r;
    Xs[r][c]=(j<N)? X[j*64+c] : 0.f;
  }
  __syncthreads();
  ull acc2[4][4];
  #pragma unroll
  for(int i=0;i<4;i++)
    #pragma unroll
    for(int j=0;j<4;j++) acc2[i][j]=0ull;
  const ull* Gp[4]; const ull* Xp[4];
  #pragma unroll
  for(int i=0;i<4;i++){ Gp[i]=(const ull*)&Gs[ty+16*i][0]; Xp[i]=(const ull*)&Xs[tx+16*i][0]; }
  #pragma unroll 8
  for(int k2=0;k2<32;k2++){
    ull g[4],x[4];
    #pragma unroll
    for(int i=0;i<4;i++){ g[i]=Gp[i][k2]; x[i]=Xp[i][k2]; }
    #pragma unroll
    for(int i=0;i<4;i++)
      #pragma unroll
      for(int j=0;j<4;j++) acc2[i][j]=fma2(g[i],x[j],acc2[i][j]);
  }
  #pragma unroll
  for(int i=0;i<4;i++){
    float s=0.f;
    #pragma unroll
    for(int j=0;j<4;j++){
      int jj=j0+tx+16*j;
      float lo=__uint_as_float((unsigned)(acc2[i][j]&0xffffffffull));
      float hi=__uint_as_float((unsigned)(acc2[i][j]>>32));
      if(jj<N) s+=exp2f(lo+hi);
    }
    Ps[ty+16*i][tx]=s;
  }
  __syncthreads();
  if(tid<64){
    float s=0.f;
    #pragma unroll
    for(int t=0;t<16;t++) s+=Ps[tid][t];
    atomicAdd(&g_negS[isItem*BB + b0 + tid],(double)s);
  }
}

__global__ void k_final(float* __restrict__ out){
  __shared__ double sh[1024];
  int t=threadIdx.x;
  sh[t]=log(g_negS[t]+1e-8)+log(g_negS[BB+t]+1e-8);
  __syncthreads();
  for(int o=512;o;o>>=1){ if(t<o) sh[t]+=sh[t+o]; __syncthreads(); }
  if(t==0){
    double neg=sh[0]/(double)BB;
    double pos=g_acc[3]/(double)BB;
    double cl=-pos+neg;
    double bpr=g_acc[2]/(double)BB;
    double pr=0.01*(g_acc[0]/(double)NE);
    double reg=1e-5*g_acc[1];
    out[0]=(float)(bpr+0.2*cl+pr+reg);
    out[1]=(float)bpr;
    out[2]=(float)(0.2*cl);
    out[3]=(float)pr;
  }
}

#define GA(p,s) do{ void* t_=0; cudaGetSymbolAddress(&t_,s); p=(decltype(p))t_; }while(0)

extern "C" void kernel_launch(void* const* d_in, const int* in_sizes, int n_in,
                              void* d_out, int out_size){
  const float* E_u_0 =(const float*)d_in[0];
  const float* E_i_0 =(const float*)d_in[1];
  const float* fuse_w=(const float*)d_in[2];
  const float* fuse_b=(const float*)d_in[3];
  const float* W1u   =(const float*)d_in[4];
  const float* W1i   =(const float*)d_in[5];
  const float* b1    =(const float*)d_in[6];
  const float* W2    =(const float*)d_in[7];
  const float* b2    =(const float*)d_in[8];
  const float* att_a =(const float*)d_in[9];
  const float* wv    =(const float*)d_in[10];
  const float* Wg    =(const float*)d_in[11];
  const float* adj   =(const float*)d_in[12];
  const float* dm    =(const float*)d_in[13];
  const float* da    =(const float*)d_in[14];
  const int* esrc=(const int*)d_in[15];
  const int* edst=(const int*)d_in[16];
  const int* uids=(const int*)d_in[17];
  const int* iids=(const int*)d_in[18];
  const int* pos =(const int*)d_in[19];
  const int* neg =(const int*)d_in[20];
  float* out=(float*)d_out;

  float *Eu1,*EuS,*U1,*Hg,*hu,*Zu,*Ei1,*EiS,*I1,*hi,*Zi,*au,*ai;
  float *wcu,*wci,*wm0u,*wm1u,*wm0i,*wm1i,*wa0u,*wa1u,*wa0i,*wa1i;
  int *rpu,*rpi,*cu,*ci,*du,*di,*pu,*pi,*colu,*coli;
  GA(Eu1,g_Eu1); GA(EuS,g_EuS); GA(U1,g_U1); GA(Hg,g_Hg);
  GA(hu,g_hu); GA(Zu,g_Zu); GA(Ei1,g_Ei1); GA(EiS,g_EiS);
  GA(I1,g_I1); GA(hi,g_hi); GA(Zi,g_Zi); GA(au,g_au); GA(ai,g_ai);
  GA(wcu,g_wcu); GA(wci,g_wci); GA(wm0u,g_wm0u); GA(wm1u,g_wm1u);
  GA(wm0i,g_wm0i); GA(wm1i,g_wm1i); GA(wa0u,g_wa0u); GA(wa1u,g_wa1u);
  GA(wa0i,g_wa0i); GA(wa1i,g_wa1i);
  GA(rpu,g_rowptr_u); GA(rpi,g_rowptr_i); GA(cu,g_cur_u); GA(ci,g_cur_i);
  GA(du,g_deg_u); GA(di,g_deg_i); GA(pu,g_part_u); GA(pi,g_part_i);
  GA(colu,g_col_u); GA(coli,g_col_i);

  dim3 b256(256), bg(16,16);
  int gU=(NU+15)/16, gI=(NI+15)/16;
  int nbU=(NU+255)/256, nbI=(NI+255)/256;

  k_init<<<391,b256>>>();
  k_gemm_node<<<gU,bg>>>(E_u_0,W1u,b1,att_a,U1,au,NU);
  k_gemm_node<<<gI,bg>>>(E_i_0,W1i,0,att_a+64,I1,ai,NI);
  k_count<<<(NE+255)/256,b256>>>(esrc,edst);
  k_scanA<<<nbU,b256>>>(du,NU,pu);
  k_scanA<<<nbI,b256>>>(di,NI,pi);
  k_scanB<<<1,512>>>(pu,nbU);
  k_scanB<<<1,512>>>(pi,nbI);
  k_scanC<<<nbU,b256>>>(du,NU,pu,rpu,cu);
  k_scanC<<<nbI,b256>>>(di,NI,pi,rpi,ci);
  k_fill<<<(NE+255)/256,b256>>>(esrc,edst);
  k_permw<<<(2*NE+255)/256,b256>>>(adj,dm);

  // main propagation (2 layers), layer-2 fused with sum
  k_spmm<<<gU,b256>>>(rpu,colu,wm0u,E_i_0,0,0,Eu1,NU);
  k_spmm<<<gI,b256>>>(rpi,coli,wm0i,E_u_0,0,0,Ei1,NI);
  k_spmm<<<gU,b256>>>(rpu,colu,wm1u,Ei1,E_u_0,Eu1,EuS,NU);
  k_spmm<<<gI,b256>>>(rpi,coli,wm1i,Eu1,E_i_0,Ei1,EiS,NI);

  // GCN view: one clean propagation on (EuS, EiS)
  k_spmm<<<gU,b256>>>(rpu,colu,wcu,EiS,0,0,hu,NU);
  k_spmm<<<gI,b256>>>(rpi,coli,wci,EuS,0,0,hi,NI);
  k_gemm_node<<<gU,bg>>>(hu,Wg,0,0,Hg,0,NU);

  // edge passes
  k_edge1<<<(NI+7)/8,b256>>>(W2,b2,wv,fuse_w,fuse_b);
  k_edge2<<<(NE+255)/256,b256>>>(fuse_w,fuse_b,adj);
  k_permaug<<<(2*NE+255)/256,b256>>>(da);

  // augmented propagation
  k_spmm<<<gU,b256>>>(rpu,colu,wa0u,E_i_0,0,0,Eu1,NU);
  k_spmm<<<gI,b256>>>(rpi,coli,wa0i,E_u_0,0,0,Ei1,NI);
  k_spmm<<<gU,b256>>>(rpu,colu,wa1u,Ei1,E_u_0,Eu1,Zu,NU);
  k_spmm<<<gI,b256>>>(rpi,coli,wa1i,Eu1,E_i_0,Ei1,Zi,NI);

  // regularization
  k_sqsum<<<512,b256>>>(E_u_0,NU*64);
  k_sqsum<<<512,b256>>>(E_i_0,NI*64);
  k_sqsum3<<<512,b256>>>(fuse_w,fuse_b,wv,NE);
  k_sqsum_small<<<16,b256>>>(W1u,W1i,b1,W2,b2,att_a,Wg);

  // batch losses
  k_small<<<(BB*32+255)/256,b256>>>(uids,iids,pos,neg);
  dim3 bn(16,16);
  k_negsum<<<dim3((NU+63)/64,BB/64),bn>>>(uids,Zu,EuS,NU,0);
  k_negsum<<<dim3((NI+63)/64,BB/64),bn>>>(iids,Zi,EiS,NI,1);

  k_final<<<1,1024>>>(out);
}

// round 7
// speedup vs baseline: 2.0401x; 1.2325x over previous
#include <cuda_runtime.h>
#include <math.h>

#define NU 100000
#define NI 50000
#define NE 800000
#define BB 1024
typedef unsigned long long ull;

__device__ float g_Eu1[NU*64];
__device__ float g_EuS[NU*64];
__device__ float g_U1 [NU*64];
__device__ float g_Hg [NU*64];
__device__ float g_hu [NU*64];
__device__ float g_Zu [NU*64];
__device__ float g_Ei1[NI*64];
__device__ float g_EiS[NI*64];
__device__ float g_I1 [NI*64];
__device__ float g_hi [NI*64];
__device__ float g_Zi [NI*64];
__device__ float g_au[NU];
__device__ float g_ai[NI];
__device__ float g_views[4*NE];
__device__ float g_pre[NE];
__device__ float g_aug[NE];
__device__ int   g_rowptr_u[NU+1];
__device__ int   g_rowptr_i[NI+1];
__device__ int   g_cur_u[NU];
__device__ int   g_cur_i[NI];
__device__ int   g_deg_u[NU];
__device__ int   g_deg_i[NI];
__device__ int   g_part_u[512];
__device__ int   g_part_i[512];
__device__ int   g_col_u[NE];
__device__ int   g_eid_u[NE];
__device__ int   g_col_i[NE];
__device__ int   g_eid_i[NE];
__device__ float g_wcu[NE],  g_wci[NE];
__device__ float g_wm0u[NE], g_wm1u[NE];
__device__ float g_wm0i[NE], g_wm1i[NE];
__device__ float g_wa0u[NE], g_wa1u[NE];
__device__ float g_wa0i[NE], g_wa1i[NE];
__device__ double g_expsum[4];
__device__ double g_acc[4];     // 0: pr, 1: reg, 2: bpr, 3: pos
__device__ double g_negS[2*BB];

__device__ __forceinline__ float sigf(float x){ return 1.f/(1.f+expf(-x)); }
__device__ __forceinline__ unsigned tf32c(float f){
  unsigned u; asm("cvt.rna.tf32.f32 %0, %1;":"=r"(u):"f"(f)); return u;
}

__global__ void k_init(){
  int i=blockIdx.x*blockDim.x+threadIdx.x, st=gridDim.x*blockDim.x;
  for(int t=i;t<NU;t+=st) g_deg_u[t]=0;
  for(int t=i;t<NI;t+=st) g_deg_i[t]=0;
  for(int t=i;t<2*BB;t+=st) g_negS[t]=0.0;
  if(i<4){ g_expsum[i]=0.0; g_acc[i]=0.0; }
}

__global__ void k_count(const int* __restrict__ src, const int* __restrict__ dst){
  int e=blockIdx.x*blockDim.x+threadIdx.x;
  if(e<NE){ atomicAdd(&g_deg_u[src[e]],1); atomicAdd(&g_deg_i[dst[e]],1); }
}

// concat scans: blocks [0,nbU) -> u side, [nbU, nbU+nbI) -> i side
__global__ void k_scanA(int nbU){
  __shared__ int sh[256];
  int bu=blockIdx.x<nbU;
  const int* deg = bu? g_deg_u : g_deg_i;
  int* part      = bu? g_part_u: g_part_i;
  int blk = bu? blockIdx.x : blockIdx.x-nbU;
  int n = bu? NU:NI;
  int i=blk*256+threadIdx.x;
  sh[threadIdx.x]=(i<n)?deg[i]:0;
  __syncthreads();
  for(int o=128;o;o>>=1){ if(threadIdx.x<o) sh[threadIdx.x]+=sh[threadIdx.x+o]; __syncthreads(); }
  if(threadIdx.x==0) part[blk]=sh[0];
}
__global__ void k_scanB(int nbU, int nbI){
  __shared__ int sh[512];
  int* part = blockIdx.x? g_part_i : g_part_u;
  int nb    = blockIdx.x? nbI : nbU;
  int t=threadIdx.x;
  int v=(t<nb)?part[t]:0;
  sh[t]=v; __syncthreads();
  for(int o=1;o<512;o<<=1){ int a=(t>=o)?sh[t-o]:0; __syncthreads(); sh[t]+=a; __syncthreads(); }
  if(t<nb) part[t]=sh[t]-v;
}
__global__ void k_scanC(int nbU){
  __shared__ int sh[256];
  int bu=blockIdx.x<nbU;
  const int* deg = bu? g_deg_u : g_deg_i;
  const int* part= bu? g_part_u: g_part_i;
  int* rowptr    = bu? g_rowptr_u : g_rowptr_i;
  int* cur       = bu? g_cur_u : g_cur_i;
  int blk = bu? blockIdx.x : blockIdx.x-nbU;
  int n = bu? NU:NI;
  int i=blk*256+threadIdx.x;
  int v=(i<n)?deg[i]:0;
  sh[threadIdx.x]=v; __syncthreads();
  for(int o=1;o<256;o<<=1){ int a=(threadIdx.x>=o)?sh[threadIdx.x-o]:0; __syncthreads(); sh[threadIdx.x]+=a; __syncthreads(); }
  int excl=part[blk]+sh[threadIdx.x]-v;
  if(i<n){ rowptr[i]=excl; cur[i]=excl; }
  if(i==n-1) rowptr[n]=excl+v;
}

// fill CSR + write clean/main weights in CSR order directly
__global__ void k_fill(const int* __restrict__ src, const int* __restrict__ dst,
                       const float* __restrict__ adj, const float* __restrict__ dm){
  int e=blockIdx.x*blockDim.x+threadIdx.x;
  const float R=1.3333333333333333f;
  if(e<NE){
    int s=src[e], d=dst[e];
    float w=adj[e];
    float m0u=(dm[e]      >0.25f)? w*R:0.f;
    float m1u=(dm[2*NE+e] >0.25f)? w*R:0.f;
    float m0i=(dm[NE+e]   >0.25f)? w*R:0.f;
    float m1i=(dm[3*NE+e] >0.25f)? w*R:0.f;
    int p=atomicAdd(&g_cur_u[s],1);
    g_col_u[p]=d; g_eid_u[p]=e; g_wcu[p]=w; g_wm0u[p]=m0u; g_wm1u[p]=m1u;
    int q=atomicAdd(&g_cur_i[d],1);
    g_col_i[q]=s; g_eid_i[q]=e; g_wci[q]=w; g_wm0i[q]=m0i; g_wm1i[q]=m1i;
  }
}

__global__ void k_permaug(const float* __restrict__ da){
  int j=blockIdx.x*blockDim.x+threadIdx.x;
  const float R=1.3333333333333333f;
  if(j<NE){
    int id=g_eid_u[j]; float w=g_aug[id];
    g_wa0u[j]=(da[id]       >0.25f)? w*R:0.f;
    g_wa1u[j]=(da[2*NE+id]  >0.25f)? w*R:0.f;
  } else if(j<2*NE){
    int jj=j-NE;
    int id=g_eid_i[jj]; float w=g_aug[id];
    g_wa0i[jj]=(da[NE+id]   >0.25f)? w*R:0.f;
    g_wa1i[jj]=(da[3*NE+id] >0.25f)? w*R:0.f;
  }
}

// Y[r,:] = (A?A[r,:]:0)+(B?B[r,:]:0)+ sum_j w[j]*X[col[j],:]
__global__ void k_spmm(const int* __restrict__ rowptr, const int* __restrict__ col,
                       const float* __restrict__ w, const float* __restrict__ X,
                       const float* __restrict__ A, const float* __restrict__ Bv,
                       float* __restrict__ Y, int nrows){
  int tid=threadIdx.x;
  int warp=tid>>5, lane=tid&31;
  int half=lane>>4, sub=lane&15;
  int r=blockIdx.x*16 + warp*2 + half;
  int beg=0,end=0;
  if(r<nrows){ beg=rowptr[r]; end=rowptr[r+1]; }
  int deg=end-beg;
  int maxdeg=max(deg,__shfl_xor_sync(0xffffffffu,deg,16));
  float4 aa[4];
  #pragma unroll
  for(int q=0;q<4;q++) aa[q]=make_float4(0.f,0.f,0.f,0.f);
  for(int base=0; base<maxdeg; base+=16){
    int c=0; float v=0.f;
    if(base+sub<deg){
      int j=beg+base+sub;
      c=col[j]; v=w[j];
    }
    #pragma unroll
    for(int q=0;q<16;q++){
      float vq=__shfl_sync(0xffffffffu,v,q,16);
      int   cq=__shfl_sync(0xffffffffu,c,q,16);
      if(vq!=0.f){
        float4 x=*(const float4*)&X[cq*64+sub*4];
        aa[q&3].x+=vq*x.x; aa[q&3].y+=vq*x.y; aa[q&3].z+=vq*x.z; aa[q&3].w+=vq*x.w;
      }
    }
  }
  float4 acc;
  acc.x=(aa[0].x+aa[1].x)+(aa[2].x+aa[3].x);
  acc.y=(aa[0].y+aa[1].y)+(aa[2].y+aa[3].y);
  acc.z=(aa[0].z+aa[1].z)+(aa[2].z+aa[3].z);
  acc.w=(aa[0].w+aa[1].w)+(aa[2].w+aa[3].w);
  if(r<nrows){
    int o=r*64+sub*4;
    if(A){ float4 a=*(const float4*)&A[o]; acc.x+=a.x; acc.y+=a.y; acc.z+=a.z; acc.w+=a.w; }
    if(Bv){ float4 b=*(const float4*)&Bv[o]; acc.x+=b.x; acc.y+=b.y; acc.z+=b.z; acc.w+=b.w; }
    *(float4*)&Y[o]=acc;
  }
}

// Y = X @ W (+bias); optional fused att scalar
__global__ void k_gemm_node(const float* __restrict__ X, const float* __restrict__ W,
                            const float* __restrict__ bias, const float* __restrict__ att,
                            float* __restrict__ Y, float* __restrict__ attOut, int n){
  __shared__ float Ws[64*64];
  __shared__ float Xs[16][64];
  __shared__ float atts[64];
  int tx=threadIdx.x, ty=threadIdx.y;
  int tid=ty*16+tx;
  for(int t=tid;t<4096;t+=256) Ws[t]=W[t];
  if(att && tid<64) atts[tid]=att[tid];
  int r=blockIdx.x*16+ty;
  if(r<n) ((float4*)Xs[ty])[tx]=((const float4*)&X[r*64])[tx];
  __syncthreads();
  if(r<n){
    float4 acc = bias ? ((const float4*)bias)[tx] : make_float4(0.f,0.f,0.f,0.f);
    #pragma unroll
    for(int k=0;k<64;k++){
      float xv=Xs[ty][k];
      float4 w=((const float4*)&Ws[k*64])[tx];
      acc.x+=xv*w.x; acc.y+=xv*w.y; acc.z+=xv*w.z; acc.w+=xv*w.w;
    }
    ((float4*)&Y[r*64])[tx]=acc;
  }
  if(att){
    float p=0.f;
    if(r<n){
      #pragma unroll
      for(int d=0;d<4;d++) p+=Xs[ty][tx*4+d]*atts[tx*4+d];
    }
    #pragma unroll
    for(int o=8;o;o>>=1) p+=__shfl_xor_sync(0xffffffffu,p,o,16);
    if(r<n && tx==0) attOut[r]=p;
  }
}

// edge views, CSR-item order
__global__ void k_edge1(const float* __restrict__ W2, const float* __restrict__ b2,
                        const float* __restrict__ wv, const float* __restrict__ fw,
                        const float* __restrict__ fb){
  __shared__ float W2s[64];
  __shared__ double sacc[4];
  int tid=threadIdx.x, lane=tid&31, warp=tid>>5;
  if(tid<64) W2s[tid]=W2[tid];
  if(tid<4)  sacc[tid]=0.0;
  __syncthreads();
  int r=blockIdx.x*8+warp;
  float e0=0.f,e1=0.f,e2=0.f,e3=0.f;
  if(r<NI){
    float b2v=b2[0];
    float w2a=W2s[lane*2], w2b=W2s[lane*2+1];
    float2 i1 =*(const float2*)&g_I1 [r*64+lane*2];
    float2 hi2=*(const float2*)&g_hi [r*64+lane*2];
    float2 si =*(const float2*)&g_EiS[r*64+lane*2];
    float aiv=g_ai[r];
    int beg=g_rowptr_i[r], end=g_rowptr_i[r+1];
    for(int j=beg;j<end;j++){
      int u=g_col_i[j];
      float2 u1=*(const float2*)&g_U1 [u*64+lane*2];
      float2 hg=*(const float2*)&g_Hg [u*64+lane*2];
      float2 su=*(const float2*)&g_EuS[u*64+lane*2];
      float m  = fmaxf(u1.x+i1.x,0.f)*w2a + fmaxf(u1.y+i1.y,0.f)*w2b;
      float gc = hg.x*hi2.x + hg.y*hi2.y;
      float pr = su.x*si.x + su.y*si.y;
      #pragma unroll
      for(int o=16;o;o>>=1){
        m +=__shfl_xor_sync(0xffffffffu,m,o);
        gc+=__shfl_xor_sync(0xffffffffu,gc,o);
        pr+=__shfl_xor_sync(0xffffffffu,pr,o);
      }
      if(lane==0){
        int e=g_eid_i[j];
        float v0=sigf(m+b2v);
        float v1=sigf(wv[e]);
        float v2=sigf(gc);
        float a=g_au[u]+aiv;
        float v3=sigf(a>0.f? a : 0.2f*a);
        g_views[e]=v0; g_views[NE+e]=v1; g_views[2*NE+e]=v2; g_views[3*NE+e]=v3;
        g_pre[e]=sigf(pr);
        float w=fw[e], b=fb[e];
        e0+=expf(tanhf(w*v0+b));
        e1+=expf(tanhf(w*v1+b));
        e2+=expf(tanhf(w*v2+b));
        e3+=expf(tanhf(w*v3+b));
      }
    }
  }
  if(lane==0 && r<NI){
    atomicAdd(&sacc[0],(double)e0);
    atomicAdd(&sacc[1],(double)e1);
    atomicAdd(&sacc[2],(double)e2);
    atomicAdd(&sacc[3],(double)e3);
  }
  __syncthreads();
  if(tid<4) atomicAdd(&g_expsum[tid],sacc[tid]);
}

__global__ void k_edge2(const float* __restrict__ fw, const float* __restrict__ fb,
                        const float* __restrict__ adj){
  int e=blockIdx.x*blockDim.x+threadIdx.x;
  float lp=0.f;
  if(e<NE){
    float S0=(float)g_expsum[0], S1=(float)g_expsum[1];
    float S2=(float)g_expsum[2], S3=(float)g_expsum[3];
    float w=fw[e], b=fb[e];
    float v0=g_views[e], v1=g_views[NE+e], v2=g_views[2*NE+e], v3=g_views[3*NE+e];
    float Ag = expf(tanhf(w*v0+b))/S0*v0
             + expf(tanhf(w*v1+b))/S1*v1
             + expf(tanhf(w*v2+b))/S2*v2
             + expf(tanhf(w*v3+b))/S3*v3;
    float sumv=v0+v1+v2+v3;
    float baew=g_pre[e]*((sumv-3.f*Ag)*0.2f);
    g_aug[e]=baew*adj[e];
    lp=-logf(baew);
  }
  #pragma unroll
  for(int o=16;o;o>>=1) lp += __shfl_xor_sync(0xffffffffu,lp,o);
  if((threadIdx.x&31)==0) atomicAdd(&g_acc[0],(double)lp);
}

__global__ void k_sqsum(const float* __restrict__ p, int n){
  double s=0.0;
  for(int i=blockIdx.x*blockDim.x+threadIdx.x;i<n;i+=gridDim.x*blockDim.x){
    float v=p[i]; s+=(double)v*(double)v;
  }
  #pragma unroll
  for(int o=16;o;o>>=1) s += __shfl_xor_sync(0xffffffffu,s,o);
  if((threadIdx.x&31)==0) atomicAdd(&g_acc[1],s);
}

__global__ void k_sqsum3(const float* __restrict__ a, const float* __restrict__ b,
                         const float* __restrict__ c, int n){
  double s=0.0;
  for(int i=blockIdx.x*blockDim.x+threadIdx.x;i<n;i+=gridDim.x*blockDim.x){
    float x=a[i],y=b[i],z=c[i];
    s+=(double)x*x+(double)y*y+(double)z*z;
  }
  #pragma unroll
  for(int o=16;o;o>>=1) s += __shfl_xor_sync(0xffffffffu,s,o);
  if((threadIdx.x&31)==0) atomicAdd(&g_acc[1],s);
}

__global__ void k_sqsum_small(const float* __restrict__ W1u, const float* __restrict__ W1i,
                              const float* __restrict__ b1, const float* __restrict__ W2,
                              const float* __restrict__ b2, const float* __restrict__ att_a,
                              const float* __restrict__ Wg){
  const float* ps[7]={W1u,W1i,b1,W2,b2,att_a,Wg};
  const int    ln[7]={4096,4096,64,64,1,128,4096};
  double s=0.0;
  int i0=blockIdx.x*blockDim.x+threadIdx.x, st=gridDim.x*blockDim.x;
  for(int a=0;a<7;a++){
    const float* p=ps[a];
    for(int i=i0;i<ln[a];i+=st){ float v=p[i]; s+=(double)v*(double)v; }
  }
  #pragma unroll
  for(int o=16;o;o>>=1) s += __shfl_xor_sync(0xffffffffu,s,o);
  if((threadIdx.x&31)==0) atomicAdd(&g_acc[1],s);
}

__global__ void k_small(const int* __restrict__ uids, const int* __restrict__ iids,
                        const int* __restrict__ pos, const int* __restrict__ neg){
  int w=(blockIdx.x*blockDim.x+threadIdx.x)>>5;
  int l=threadIdx.x&31;
  if(w>=BB) return;
  int u=uids[w], it=iids[w], p=pos[w], ng=neg[w];
  float dzu=0,dzi=0,dup=0,dun=0;
  #pragma unroll
  for(int d=l; d<64; d+=32){
    float eu=g_EuS[u*64+d];
    dzu += g_Zu[u*64+d]*eu;
    dzi += g_Zi[it*64+d]*g_EiS[it*64+d];
    dup += eu*g_EiS[p*64+d];
    dun += eu*g_EiS[ng*64+d];
  }
  #pragma unroll
  for(int o=16;o;o>>=1){
    dzu+=__shfl_xor_sync(0xffffffffu,dzu,o);
    dzi+=__shfl_xor_sync(0xffffffffu,dzi,o);
    dup+=__shfl_xor_sync(0xffffffffu,dup,o);
    dun+=__shfl_xor_sync(0xffffffffu,dun,o);
  }
  if(l==0){
    float cu=fminf(fmaxf(dzu*5.f,-5.f),5.f);
    float ci=fminf(fmaxf(dzi*5.f,-5.f),5.f);
    float diff=dup-dun;
    float bpr=fmaxf(-diff,0.f)+log1pf(expf(-fabsf(diff)));
    atomicAdd(&g_acc[3],(double)(cu+ci));
    atomicAdd(&g_acc[2],(double)bpr);
  }
}

// per-b: sum_j exp(dot(Z[ids[b]], X[j])/T) via tf32 mma.sync; log2(e)/T folded into G
__global__ void k_negsum(const int* __restrict__ ids, const float* __restrict__ Z,
                         const float* __restrict__ X, int N, int isItem){
  __shared__ unsigned Gs[64][68];
  __shared__ unsigned Xs[64][68];
  __shared__ float Ps[64][8];
  int b0=blockIdx.y*64, j0=blockIdx.x*64;
  int tid=threadIdx.x; // 256
  const float scale=7.213475204444817f; // log2(e)/0.2
  for(int idx=tid; idx<64*16; idx+=256){
    int r=idx>>4, c4=(idx&15)*4;
    float4 g=*(const float4*)&Z[ids[b0+r]*64+c4];
    Gs[r][c4+0]=tf32c(g.x*scale); Gs[r][c4+1]=tf32c(g.y*scale);
    Gs[r][c4+2]=tf32c(g.z*scale); Gs[r][c4+3]=tf32c(g.w*scale);
    int j=j0+r;
    float4 x = (j<N)? *(const float4*)&X[j*64+c4] : make_float4(0.f,0.f,0.f,0.f);
    Xs[r][c4+0]=tf32c(x.x); Xs[r][c4+1]=tf32c(x.y);
    Xs[r][c4+2]=tf32c(x.z); Xs[r][c4+3]=tf32c(x.w);
  }
  __syncthreads();
  int w=tid>>5, lane=tid&31;
  int g=lane>>2, t=lane&3;
  int brow=(w&3)*16, jbase=(w>>2)*32;
  float c[4][4];
  #pragma unroll
  for(int nt=0;nt<4;nt++)
    #pragma unroll
    for(int q=0;q<4;q++) c[nt][q]=0.f;
  #pragma unroll
  for(int k0=0;k0<64;k0+=8){
    unsigned a0=Gs[brow+g][k0+t],   a1=Gs[brow+g+8][k0+t];
    unsigned a2=Gs[brow+g][k0+t+4], a3=Gs[brow+g+8][k0+t+4];
    #pragma unroll
    for(int nt=0;nt<4;nt++){
      unsigned bb0=Xs[jbase+nt*8+g][k0+t], bb1=Xs[jbase+nt*8+g][k0+t+4];
      asm volatile("mma.sync.aligned.m16n8k8.row.col.f32.tf32.tf32.f32 "
        "{%0,%1,%2,%3}, {%4,%5,%6,%7}, {%8,%9}, {%0,%1,%2,%3};"
        : "+f"(c[nt][0]),"+f"(c[nt][1]),"+f"(c[nt][2]),"+f"(c[nt][3])
        : "r"(a0),"r"(a1),"r"(a2),"r"(a3),"r"(bb0),"r"(bb1));
    }
  }
  float s0=0.f, s1=0.f;
  #pragma unroll
  for(int nt=0;nt<4;nt++){
    int col=j0+jbase+nt*8+2*t;
    if(col<N)   { s0+=exp2f(c[nt][0]); s1+=exp2f(c[nt][2]); }
    if(col+1<N) { s0+=exp2f(c[nt][1]); s1+=exp2f(c[nt][3]); }
  }
  int slot=(w>>2)*4+t;
  Ps[brow+g][slot]=s0;
  Ps[brow+g+8][slot]=s1;
  __syncthreads();
  if(tid<64){
    float s=0.f;
    #pragma unroll
    for(int q=0;q<8;q++) s+=Ps[tid][q];
    atomicAdd(&g_negS[isItem*BB + b0 + tid],(double)s);
  }
}

__global__ void k_final(float* __restrict__ out){
  __shared__ double sh[1024];
  int t=threadIdx.x;
  sh[t]=log(g_negS[t]+1e-8)+log(g_negS[BB+t]+1e-8);
  __syncthreads();
  for(int o=512;o;o>>=1){ if(t<o) sh[t]+=sh[t+o]; __syncthreads(); }
  if(t==0){
    double neg=sh[0]/(double)BB;
    double pos=g_acc[3]/(double)BB;
    double cl=-pos+neg;
    double bpr=g_acc[2]/(double)BB;
    double pr=0.01*(g_acc[0]/(double)NE);
    double reg=1e-5*g_acc[1];
    out[0]=(float)(bpr+0.2*cl+pr+reg);
    out[1]=(float)bpr;
    out[2]=(float)(0.2*cl);
    out[3]=(float)pr;
  }
}

#define GA(p,s) do{ void* t_=0; cudaGetSymbolAddress(&t_,s); p=(decltype(p))t_; }while(0)

extern "C" void kernel_launch(void* const* d_in, const int* in_sizes, int n_in,
                              void* d_out, int out_size){
  const float* E_u_0 =(const float*)d_in[0];
  const float* E_i_0 =(const float*)d_in[1];
  const float* fuse_w=(const float*)d_in[2];
  const float* fuse_b=(const float*)d_in[3];
  const float* W1u   =(const float*)d_in[4];
  const float* W1i   =(const float*)d_in[5];
  const float* b1    =(const float*)d_in[6];
  const float* W2    =(const float*)d_in[7];
  const float* b2    =(const float*)d_in[8];
  const float* att_a =(const float*)d_in[9];
  const float* wv    =(const float*)d_in[10];
  const float* Wg    =(const float*)d_in[11];
  const float* adj   =(const float*)d_in[12];
  const float* dm    =(const float*)d_in[13];
  const float* da    =(const float*)d_in[14];
  const int* esrc=(const int*)d_in[15];
  const int* edst=(const int*)d_in[16];
  const int* uids=(const int*)d_in[17];
  const int* iids=(const int*)d_in[18];
  const int* pos =(const int*)d_in[19];
  const int* neg =(const int*)d_in[20];
  float* out=(float*)d_out;

  float *Eu1,*EuS,*U1,*Hg,*hu,*Zu,*Ei1,*EiS,*I1,*hi,*Zi;
  float *wcu,*wci,*wm0u,*wm1u,*wm0i,*wm1i,*wa0u,*wa1u,*wa0i,*wa1i;
  float *au,*ai;
  int *rpu,*rpi,*colu,*coli;
  GA(Eu1,g_Eu1); GA(EuS,g_EuS); GA(U1,g_U1); GA(Hg,g_Hg);
  GA(hu,g_hu); GA(Zu,g_Zu); GA(Ei1,g_Ei1); GA(EiS,g_EiS);
  GA(I1,g_I1); GA(hi,g_hi); GA(Zi,g_Zi); GA(au,g_au); GA(ai,g_ai);
  GA(wcu,g_wcu); GA(wci,g_wci); GA(wm0u,g_wm0u); GA(wm1u,g_wm1u);
  GA(wm0i,g_wm0i); GA(wm1i,g_wm1i); GA(wa0u,g_wa0u); GA(wa1u,g_wa1u);
  GA(wa0i,g_wa0i); GA(wa1i,g_wa1i);
  GA(rpu,g_rowptr_u); GA(rpi,g_rowptr_i);
  GA(colu,g_col_u); GA(coli,g_col_i);

  dim3 b256(256), bg(16,16);
  int gU=(NU+15)/16, gI=(NI+15)/16;
  int nbU=(NU+255)/256, nbI=(NI+255)/256;

  k_init<<<391,b256>>>();
  k_count<<<(NE+255)/256,b256>>>(esrc,edst);
  k_scanA<<<nbU+nbI,b256>>>(nbU);
  k_scanB<<<2,512>>>(nbU,nbI);
  k_scanC<<<nbU+nbI,b256>>>(nbU);
  k_fill<<<(NE+255)/256,b256>>>(esrc,edst,adj,dm);

  k_gemm_node<<<gU,bg>>>(E_u_0,W1u,b1,att_a,U1,au,NU);
  k_gemm_node<<<gI,bg>>>(E_i_0,W1i,0,att_a+64,I1,ai,NI);

  // main propagation (2 layers), layer-2 fused with sum
  k_spmm<<<gU,b256>>>(rpu,colu,wm0u,E_i_0,0,0,Eu1,NU);
  k_spmm<<<gI,b256>>>(rpi,coli,wm0i,E_u_0,0,0,Ei1,NI);
  k_spmm<<<gU,b256>>>(rpu,colu,wm1u,Ei1,E_u_0,Eu1,EuS,NU);
  k_spmm<<<gI,b256>>>(rpi,coli,wm1i,Eu1,E_i_0,Ei1,EiS,NI);

  // GCN view: one clean propagation on (EuS, EiS)
  k_spmm<<<gU,b256>>>(rpu,colu,wcu,EiS,0,0,hu,NU);
  k_spmm<<<gI,b256>>>(rpi,coli,wci,EuS,0,0,hi,NI);
  k_gemm_node<<<gU,bg>>>(hu,Wg,0,0,Hg,0,NU);

  // edge passes
  k_edge1<<<(NI+7)/8,b256>>>(W2,b2,wv,fuse_w,fuse_b);
  k_edge2<<<(NE+255)/256,b256>>>(fuse_w,fuse_b,adj);
  k_permaug<<<(2*NE+255)/256,b256>>>(da);

  // augmented propagation
  k_spmm<<<gU,b256>>>(rpu,colu,wa0u,E_i_0,0,0,Eu1,NU);
  k_spmm<<<gI,b256>>>(rpi,coli,wa0i,E_u_0,0,0,Ei1,NI);
  k_spmm<<<gU,b256>>>(rpu,colu,wa1u,Ei1,E_u_0,Eu1,Zu,NU);
  k_spmm<<<gI,b256>>>(rpi,coli,wa1i,Eu1,E_i_0,Ei1,Zi,NI);

  // regularization
  k_sqsum<<<512,b256>>>(E_u_0,NU*64);
  k_sqsum<<<512,b256>>>(E_i_0,NI*64);
  k_sqsum3<<<512,b256>>>(fuse_w,fuse_b,wv,NE);
  k_sqsum_small<<<16,b256>>>(W1u,W1i,b1,W2,b2,att_a,Wg);

  // batch losses
  k_small<<<(BB*32+255)/256,b256>>>(uids,iids,pos,neg);
  k_negsum<<<dim3((NU+63)/64,BB/64),b256>>>(uids,Zu,EuS,NU,0);
  k_negsum<<<dim3((NI+63)/64,BB/64),b256>>>(iids,Zi,EiS,NI,1);

  k_final<<<1,1024>>>(out);
}

// round 8
// speedup vs baseline: 2.2897x; 1.1223x over previous
#include <cuda_runtime.h>
#include <math.h>

#define NU 100000
#define NI 50000
#define NE 800000
#define BB 1024
typedef unsigned long long ull;

__device__ float g_Eu1[NU*64];
__device__ float g_EuS[NU*64];
__device__ float g_U1 [NU*64];
__device__ float g_Hg [NU*64];
__device__ float g_hu [NU*64];
__device__ float g_Zu [NU*64];
__device__ float g_Ei1[NI*64];
__device__ float g_EiS[NI*64];
__device__ float g_I1 [NI*64];
__device__ float g_hi [NI*64];
__device__ float g_Zi [NI*64];
__device__ float g_au[NU];
__device__ float g_ai[NI];
__device__ float g_views[4*NE];
__device__ float g_pre[NE];
__device__ int   g_rowptr_u[NU+1];
__device__ int   g_rowptr_i[NI+1];
__device__ int   g_cur_u[NU];
__device__ int   g_cur_i[NI];
__device__ int   g_deg_u[NU];
__device__ int   g_deg_i[NI];
__device__ int   g_part_u[512];
__device__ int   g_part_i[512];
__device__ int   g_col_u[NE];
__device__ int   g_col_i[NE];
__device__ int   g_eid_i[NE];
__device__ int   g_pos_u[NE];
__device__ int   g_pos_i[NE];
__device__ float g_fwi[NE], g_fbi[NE], g_wvi[NE];
__device__ float g_wcu[NE],  g_wci[NE];
__device__ float g_wm0u[NE], g_wm1u[NE];
__device__ float g_wm0i[NE], g_wm1i[NE];
__device__ float g_wa0u[NE], g_wa1u[NE];
__device__ float g_wa0i[NE], g_wa1i[NE];
__device__ double g_expsum[4];
__device__ double g_acc[4];     // 0: pr, 1: reg, 2: bpr, 3: pos
__device__ double g_negS[2*BB];

__device__ __forceinline__ float sigf(float x){ return 1.f/(1.f+__expf(-x)); }
__device__ __forceinline__ float tanha(float x){
  float y; asm("tanh.approx.f32 %0, %1;":"=f"(y):"f"(x)); return y;
}
__device__ __forceinline__ unsigned tf32c(float f){
  unsigned u; asm("cvt.rna.tf32.f32 %0, %1;":"=r"(u):"f"(f)); return u;
}

__global__ void k_init(){
  int i=blockIdx.x*blockDim.x+threadIdx.x, st=gridDim.x*blockDim.x;
  for(int t=i;t<NU;t+=st) g_deg_u[t]=0;
  for(int t=i;t<NI;t+=st) g_deg_i[t]=0;
  for(int t=i;t<2*BB;t+=st) g_negS[t]=0.0;
  if(i<4){ g_expsum[i]=0.0; g_acc[i]=0.0; }
}

__global__ void k_count(const int* __restrict__ src, const int* __restrict__ dst){
  int e=blockIdx.x*blockDim.x+threadIdx.x;
  if(e<NE){ atomicAdd(&g_deg_u[src[e]],1); atomicAdd(&g_deg_i[dst[e]],1); }
}

__global__ void k_scanA(int nbU){
  __shared__ int sh[256];
  int bu=blockIdx.x<nbU;
  const int* deg = bu? g_deg_u : g_deg_i;
  int* part      = bu? g_part_u: g_part_i;
  int blk = bu? blockIdx.x : blockIdx.x-nbU;
  int n = bu? NU:NI;
  int i=blk*256+threadIdx.x;
  sh[threadIdx.x]=(i<n)?deg[i]:0;
  __syncthreads();
  for(int o=128;o;o>>=1){ if(threadIdx.x<o) sh[threadIdx.x]+=sh[threadIdx.x+o]; __syncthreads(); }
  if(threadIdx.x==0) part[blk]=sh[0];
}
__global__ void k_scanB(int nbU, int nbI){
  __shared__ int sh[512];
  int* part = blockIdx.x? g_part_i : g_part_u;
  int nb    = blockIdx.x? nbI : nbU;
  int t=threadIdx.x;
  int v=(t<nb)?part[t]:0;
  sh[t]=v; __syncthreads();
  for(int o=1;o<512;o<<=1){ int a=(t>=o)?sh[t-o]:0; __syncthreads(); sh[t]+=a; __syncthreads(); }
  if(t<nb) part[t]=sh[t]-v;
}
__global__ void k_scanC(int nbU){
  __shared__ int sh[256];
  int bu=blockIdx.x<nbU;
  const int* deg = bu? g_deg_u : g_deg_i;
  const int* part= bu? g_part_u: g_part_i;
  int* rowptr    = bu? g_rowptr_u : g_rowptr_i;
  int* cur       = bu? g_cur_u : g_cur_i;
  int blk = bu? blockIdx.x : blockIdx.x-nbU;
  int n = bu? NU:NI;
  int i=blk*256+threadIdx.x;
  int v=(i<n)?deg[i]:0;
  sh[threadIdx.x]=v; __syncthreads();
  for(int o=1;o<256;o<<=1){ int a=(threadIdx.x>=o)?sh[threadIdx.x-o]:0; __syncthreads(); sh[threadIdx.x]+=a; __syncthreads(); }
  int excl=part[blk]+sh[threadIdx.x]-v;
  if(i<n){ rowptr[i]=excl; cur[i]=excl; }
  if(i==n-1) rowptr[n]=excl+v;
}

// CSR fill + CSR-ordered weights + inverse positions + CSR copies of fw/fb/wv
__global__ void k_fill(const int* __restrict__ src, const int* __restrict__ dst,
                       const float* __restrict__ adj, const float* __restrict__ dm,
                       const float* __restrict__ fw, const float* __restrict__ fb,
                       const float* __restrict__ wv){
  int e=blockIdx.x*blockDim.x+threadIdx.x;
  const float R=1.3333333333333333f;
  if(e<NE){
    int s=src[e], d=dst[e];
    float w=adj[e];
    float m0u=(dm[e]      >0.25f)? w*R:0.f;
    float m1u=(dm[2*NE+e] >0.25f)? w*R:0.f;
    float m0i=(dm[NE+e]   >0.25f)? w*R:0.f;
    float m1i=(dm[3*NE+e] >0.25f)? w*R:0.f;
    int p=atomicAdd(&g_cur_u[s],1);
    g_col_u[p]=d; g_wcu[p]=w; g_wm0u[p]=m0u; g_wm1u[p]=m1u;
    g_pos_u[e]=p;
    int q=atomicAdd(&g_cur_i[d],1);
    g_col_i[q]=s; g_eid_i[q]=e; g_wci[q]=w; g_wm0i[q]=m0i; g_wm1i[q]=m1i;
    g_fwi[q]=fw[e]; g_fbi[q]=fb[e]; g_wvi[q]=wv[e];
    g_pos_i[e]=q;
  }
}

// dual-side SpMM: blocks [0,gA) side A, [gA,..) side B
__device__ __forceinline__ void spmm_body(const int* rowptr, const int* col,
                       const float* w, const float* X,
                       const float* A, const float* Bv,
                       float* Y, int nrows, int blk){
  int tid=threadIdx.x;
  int warp=tid>>5, lane=tid&31;
  int half=lane>>4, sub=lane&15;
  int r=blk*16 + warp*2 + half;
  int beg=0,end=0;
  if(r<nrows){ beg=rowptr[r]; end=rowptr[r+1]; }
  int deg=end-beg;
  int maxdeg=max(deg,__shfl_xor_sync(0xffffffffu,deg,16));
  float4 aa[4];
  #pragma unroll
  for(int q=0;q<4;q++) aa[q]=make_float4(0.f,0.f,0.f,0.f);
  for(int base=0; base<maxdeg; base+=16){
    int c=0; float v=0.f;
    if(base+sub<deg){
      int j=beg+base+sub;
      c=col[j]; v=w[j];
    }
    #pragma unroll
    for(int q=0;q<16;q++){
      float vq=__shfl_sync(0xffffffffu,v,q,16);
      int   cq=__shfl_sync(0xffffffffu,c,q,16);
      if(vq!=0.f){
        float4 x=*(const float4*)&X[cq*64+sub*4];
        aa[q&3].x+=vq*x.x; aa[q&3].y+=vq*x.y; aa[q&3].z+=vq*x.z; aa[q&3].w+=vq*x.w;
      }
    }
  }
  float4 acc;
  acc.x=(aa[0].x+aa[1].x)+(aa[2].x+aa[3].x);
  acc.y=(aa[0].y+aa[1].y)+(aa[2].y+aa[3].y);
  acc.z=(aa[0].z+aa[1].z)+(aa[2].z+aa[3].z);
  acc.w=(aa[0].w+aa[1].w)+(aa[2].w+aa[3].w);
  if(r<nrows){
    int o=r*64+sub*4;
    if(A){ float4 a=*(const float4*)&A[o]; acc.x+=a.x; acc.y+=a.y; acc.z+=a.z; acc.w+=a.w; }
    if(Bv){ float4 b=*(const float4*)&Bv[o]; acc.x+=b.x; acc.y+=b.y; acc.z+=b.z; acc.w+=b.w; }
    *(float4*)&Y[o]=acc;
  }
}
__global__ void k_spmm2(const int* ra, const int* ca, const float* wa, const float* Xa,
                        const float* Aa, const float* Ba, float* Ya, int na,
                        const int* rb, const int* cb, const float* wb, const float* Xb,
                        const float* Ab, const float* Bb, float* Yb, int nb, int gA){
  if((int)blockIdx.x<gA) spmm_body(ra,ca,wa,Xa,Aa,Ba,Ya,na,blockIdx.x);
  else                   spmm_body(rb,cb,wb,Xb,Ab,Bb,Yb,nb,blockIdx.x-gA);
}

// dual node GEMM: Y = X @ W (+bias), optional att scalar
__device__ __forceinline__ void gemm_body(const float* X, const float* W,
                            const float* bias, const float* att,
                            float* Y, float* attOut, int n, int blk){
  __shared__ float Ws[64*64];
  __shared__ float Xs[16][64];
  __shared__ float atts[64];
  int tx=threadIdx.x, ty=threadIdx.y;
  int tid=ty*16+tx;
  for(int t=tid;t<4096;t+=256) Ws[t]=W[t];
  if(att && tid<64) atts[tid]=att[tid];
  int r=blk*16+ty;
  if(r<n) ((float4*)Xs[ty])[tx]=((const float4*)&X[r*64])[tx];
  __syncthreads();
  if(r<n){
    float4 acc = bias ? ((const float4*)bias)[tx] : make_float4(0.f,0.f,0.f,0.f);
    #pragma unroll
    for(int k=0;k<64;k++){
      float xv=Xs[ty][k];
      float4 w=((const float4*)&Ws[k*64])[tx];
      acc.x+=xv*w.x; acc.y+=xv*w.y; acc.z+=xv*w.z; acc.w+=xv*w.w;
    }
    ((float4*)&Y[r*64])[tx]=acc;
  }
  if(att){
    float p=0.f;
    if(r<n){
      #pragma unroll
      for(int d=0;d<4;d++) p+=Xs[ty][tx*4+d]*atts[tx*4+d];
    }
    #pragma unroll
    for(int o=8;o;o>>=1) p+=__shfl_xor_sync(0xffffffffu,p,o,16);
    if(r<n && tx==0) attOut[r]=p;
  }
}
__global__ void k_gemm2(const float* Xa, const float* Wa, const float* ba, const float* aa,
                        float* Ya, float* aoa, int na,
                        const float* Xb, const float* Wb, const float* bb, const float* ab,
                        float* Yb, float* aob, int nb, int gA){
  if((int)blockIdx.x<gA) gemm_body(Xa,Wa,ba,aa,Ya,aoa,na,blockIdx.x);
  else                   gemm_body(Xb,Wb,bb,ab,Yb,aob,nb,blockIdx.x-gA);
}

// edge views, CSR-item order: warp per item row, 2 edges x 16 lanes x float4
__global__ void k_edge1(const float* __restrict__ W2, const float* __restrict__ b2){
  __shared__ float W2s[64];
  __shared__ double sacc[4];
  int tid=threadIdx.x, lane=tid&31, warp=tid>>5;
  int half=lane>>4, sub=lane&15;
  if(tid<64) W2s[tid]=W2[tid];
  if(tid<4)  sacc[tid]=0.0;
  __syncthreads();
  int r=blockIdx.x*8+warp;
  float e0=0.f,e1=0.f,e2=0.f,e3=0.f;
  if(r<NI){
    float b2v=b2[0];
    float4 w2=((const float4*)W2s)[sub];
    float4 i1=*(const float4*)&g_I1 [r*64+sub*4];
    float4 hi=*(const float4*)&g_hi [r*64+sub*4];
    float4 si=*(const float4*)&g_EiS[r*64+sub*4];
    float aiv=g_ai[r];
    int beg=g_rowptr_i[r], end=g_rowptr_i[r+1];
    for(int j0=beg;j0<end;j0+=2){
      int j=j0+half;
      bool act=(j<end);
      int u=g_col_i[act? j : end-1];
      const float4* U1p=(const float4*)&g_U1 [u*64];
      const float4* Hgp=(const float4*)&g_Hg [u*64];
      const float4* Sup=(const float4*)&g_EuS[u*64];
      float4 u1=U1p[sub], hg=Hgp[sub], su=Sup[sub];
      float m  = fmaxf(u1.x+i1.x,0.f)*w2.x + fmaxf(u1.y+i1.y,0.f)*w2.y
               + fmaxf(u1.z+i1.z,0.f)*w2.z + fmaxf(u1.w+i1.w,0.f)*w2.w;
      float gc = hg.x*hi.x+hg.y*hi.y+hg.z*hi.z+hg.w*hi.w;
      float pr = su.x*si.x+su.y*si.y+su.z*si.z+su.w*si.w;
      #pragma unroll
      for(int o=8;o;o>>=1){
        m +=__shfl_xor_sync(0xffffffffu,m,o,16);
        gc+=__shfl_xor_sync(0xffffffffu,gc,o,16);
        pr+=__shfl_xor_sync(0xffffffffu,pr,o,16);
      }
      if(act && sub==0){
        int e=g_eid_i[j];
        float v0=sigf(m+b2v);
        float v1=sigf(g_wvi[j]);
        float v2=sigf(gc);
        float a=g_au[u]+aiv;
        float v3=sigf(a>0.f? a : 0.2f*a);
        g_views[e]=v0; g_views[NE+e]=v1; g_views[2*NE+e]=v2; g_views[3*NE+e]=v3;
        g_pre[e]=sigf(pr);
        float w=g_fwi[j], b=g_fbi[j];
        e0+=__expf(tanha(w*v0+b));
        e1+=__expf(tanha(w*v1+b));
        e2+=__expf(tanha(w*v2+b));
        e3+=__expf(tanha(w*v3+b));
      }
    }
  }
  e0+=__shfl_xor_sync(0xffffffffu,e0,16);
  e1+=__shfl_xor_sync(0xffffffffu,e1,16);
  e2+=__shfl_xor_sync(0xffffffffu,e2,16);
  e3+=__shfl_xor_sync(0xffffffffu,e3,16);
  if(lane==0 && r<NI){
    atomicAdd(&sacc[0],(double)e0);
    atomicAdd(&sacc[1],(double)e1);
    atomicAdd(&sacc[2],(double)e2);
    atomicAdd(&sacc[3],(double)e3);
  }
  __syncthreads();
  if(tid<4) atomicAdd(&g_expsum[tid],sacc[tid]);
}

// fuse views -> baew -> aug weights scattered into CSR orders, pr loss
__global__ void k_edge2(const float* __restrict__ fw, const float* __restrict__ fb,
                        const float* __restrict__ adj, const float* __restrict__ da){
  int e=blockIdx.x*blockDim.x+threadIdx.x;
  const float R=1.3333333333333333f;
  float lp=0.f;
  if(e<NE){
    float S0=(float)g_expsum[0], S1=(float)g_expsum[1];
    float S2=(float)g_expsum[2], S3=(float)g_expsum[3];
    float w=fw[e], b=fb[e];
    float v0=g_views[e], v1=g_views[NE+e], v2=g_views[2*NE+e], v3=g_views[3*NE+e];
    float Ag = __expf(tanha(w*v0+b))/S0*v0
             + __expf(tanha(w*v1+b))/S1*v1
             + __expf(tanha(w*v2+b))/S2*v2
             + __expf(tanha(w*v3+b))/S3*v3;
    float sumv=v0+v1+v2+v3;
    float baew=g_pre[e]*((sumv-3.f*Ag)*0.2f);
    float augw=baew*adj[e];
    int pu=g_pos_u[e], pi=g_pos_i[e];
    g_wa0u[pu]=(da[e]      >0.25f)? augw*R:0.f;
    g_wa1u[pu]=(da[2*NE+e] >0.25f)? augw*R:0.f;
    g_wa0i[pi]=(da[NE+e]   >0.25f)? augw*R:0.f;
    g_wa1i[pi]=(da[3*NE+e] >0.25f)? augw*R:0.f;
    lp=-__logf(baew);
  }
  #pragma unroll
  for(int o=16;o;o>>=1) lp += __shfl_xor_sync(0xffffffffu,lp,o);
  if((threadIdx.x&31)==0) atomicAdd(&g_acc[0],(double)lp);
}

// all regularization terms in one launch
__global__ void k_sqsum_all(const float* __restrict__ Eu0, const float* __restrict__ Ei0,
                            const float* __restrict__ fw, const float* __restrict__ fb,
                            const float* __restrict__ wv,
                            const float* __restrict__ W1u, const float* __restrict__ W1i,
                            const float* __restrict__ b1, const float* __restrict__ W2,
                            const float* __restrict__ b2, const float* __restrict__ att_a,
                            const float* __restrict__ Wg){
  double s=0.0;
  int i0=blockIdx.x*blockDim.x+threadIdx.x, st=gridDim.x*blockDim.x;
  for(int i=i0;i<NU*64;i+=st){ float v=Eu0[i]; s+=(double)v*(double)v; }
  for(int i=i0;i<NI*64;i+=st){ float v=Ei0[i]; s+=(double)v*(double)v; }
  for(int i=i0;i<NE;i+=st){
    float x=fw[i],y=fb[i],z=wv[i];
    s+=(double)x*x+(double)y*y+(double)z*z;
  }
  if(blockIdx.x==0){
    const float* ps[7]={W1u,W1i,b1,W2,b2,att_a,Wg};
    const int    ln[7]={4096,4096,64,64,1,128,4096};
    for(int a=0;a<7;a++){
      const float* p=ps[a];
      for(int i=threadIdx.x;i<ln[a];i+=blockDim.x){ float v=p[i]; s+=(double)v*(double)v; }
    }
  }
  #pragma unroll
  for(int o=16;o;o>>=1) s += __shfl_xor_sync(0xffffffffu,s,o);
  if((threadIdx.x&31)==0) atomicAdd(&g_acc[1],s);
}

__global__ void k_small(const int* __restrict__ uids, const int* __restrict__ iids,
                        const int* __restrict__ pos, const int* __restrict__ neg){
  int w=(blockIdx.x*blockDim.x+threadIdx.x)>>5;
  int l=threadIdx.x&31;
  if(w>=BB) return;
  int u=uids[w], it=iids[w], p=pos[w], ng=neg[w];
  float dzu=0,dzi=0,dup=0,dun=0;
  #pragma unroll
  for(int d=l; d<64; d+=32){
    float eu=g_EuS[u*64+d];
    dzu += g_Zu[u*64+d]*eu;
    dzi += g_Zi[it*64+d]*g_EiS[it*64+d];
    dup += eu*g_EiS[p*64+d];
    dun += eu*g_EiS[ng*64+d];
  }
  #pragma unroll
  for(int o=16;o;o>>=1){
    dzu+=__shfl_xor_sync(0xffffffffu,dzu,o);
    dzi+=__shfl_xor_sync(0xffffffffu,dzi,o);
    dup+=__shfl_xor_sync(0xffffffffu,dup,o);
    dun+=__shfl_xor_sync(0xffffffffu,dun,o);
  }
  if(l==0){
    float cu=fminf(fmaxf(dzu*5.f,-5.f),5.f);
    float ci=fminf(fmaxf(dzi*5.f,-5.f),5.f);
    float diff=dup-dun;
    float bpr=fmaxf(-diff,0.f)+log1pf(expf(-fabsf(diff)));
    atomicAdd(&g_acc[3],(double)(cu+ci));
    atomicAdd(&g_acc[2],(double)bpr);
  }
}

// merged u/i: per-b sum_j exp(dot(Z[ids[b]], X[j])/T) via tf32 mma
__device__ __forceinline__ void negsum_body(const int* ids, const float* Z,
                                            const float* X, int N, int isItem, int bx){
  __shared__ unsigned Gs[64][68];
  __shared__ unsigned Xs[64][68];
  __shared__ float Ps[64][8];
  int b0=blockIdx.y*64, j0=bx*64;
  int tid=threadIdx.x;
  const float scale=7.213475204444817f; // log2(e)/0.2
  for(int idx=tid; idx<64*16; idx+=256){
    int r=idx>>4, c4=(idx&15)*4;
    float4 g=*(const float4*)&Z[ids[b0+r]*64+c4];
    Gs[r][c4+0]=tf32c(g.x*scale); Gs[r][c4+1]=tf32c(g.y*scale);
    Gs[r][c4+2]=tf32c(g.z*scale); Gs[r][c4+3]=tf32c(g.w*scale);
    int j=j0+r;
    float4 x = (j<N)? *(const float4*)&X[j*64+c4] : make_float4(0.f,0.f,0.f,0.f);
    Xs[r][c4+0]=tf32c(x.x); Xs[r][c4+1]=tf32c(x.y);
    Xs[r][c4+2]=tf32c(x.z); Xs[r][c4+3]=tf32c(x.w);
  }
  __syncthreads();
  int w=tid>>5, lane=tid&31;
  int g=lane>>2, t=lane&3;
  int brow=(w&3)*16, jbase=(w>>2)*32;
  float c[4][4];
  #pragma unroll
  for(int nt=0;nt<4;nt++)
    #pragma unroll
    for(int q=0;q<4;q++) c[nt][q]=0.f;
  #pragma unroll
  for(int k0=0;k0<64;k0+=8){
    unsigned a0=Gs[brow+g][k0+t],   a1=Gs[brow+g+8][k0+t];
    unsigned a2=Gs[brow+g][k0+t+4], a3=Gs[brow+g+8][k0+t+4];
    #pragma unroll
    for(int nt=0;nt<4;nt++){
      unsigned bb0=Xs[jbase+nt*8+g][k0+t], bb1=Xs[jbase+nt*8+g][k0+t+4];
      asm volatile("mma.sync.aligned.m16n8k8.row.col.f32.tf32.tf32.f32 "
        "{%0,%1,%2,%3}, {%4,%5,%6,%7}, {%8,%9}, {%0,%1,%2,%3};"
        : "+f"(c[nt][0]),"+f"(c[nt][1]),"+f"(c[nt][2]),"+f"(c[nt][3])
        : "r"(a0),"r"(a1),"r"(a2),"r"(a3),"r"(bb0),"r"(bb1));
    }
  }
  float s0=0.f, s1=0.f;
  #pragma unroll
  for(int nt=0;nt<4;nt++){
    int col=j0+jbase+nt*8+2*t;
    if(col<N)   { s0+=exp2f(c[nt][0]); s1+=exp2f(c[nt][2]); }
    if(col+1<N) { s0+=exp2f(c[nt][1]); s1+=exp2f(c[nt][3]); }
  }
  int slot=(w>>2)*4+t;
  Ps[brow+g][slot]=s0;
  Ps[brow+g+8][slot]=s1;
  __syncthreads();
  if(tid<64){
    float s=0.f;
    #pragma unroll
    for(int q=0;q<8;q++) s+=Ps[tid][q];
    atomicAdd(&g_negS[isItem*BB + b0 + tid],(double)s);
  }
}
__global__ void k_negsum2(const int* uids, const int* iids, int gxU){
  if((int)blockIdx.x<gxU) negsum_body(uids,g_Zu,g_EuS,NU,0,blockIdx.x);
  else                    negsum_body(iids,g_Zi,g_EiS,NI,1,blockIdx.x-gxU);
}

__global__ void k_final(float* __restrict__ out){
  __shared__ double sh[1024];
  int t=threadIdx.x;
  sh[t]=log(g_negS[t]+1e-8)+log(g_negS[BB+t]+1e-8);
  __syncthreads();
  for(int o=512;o;o>>=1){ if(t<o) sh[t]+=sh[t+o]; __syncthreads(); }
  if(t==0){
    double neg=sh[0]/(double)BB;
    double pos=g_acc[3]/(double)BB;
    double cl=-pos+neg;
    double bpr=g_acc[2]/(double)BB;
    double pr=0.01*(g_acc[0]/(double)NE);
    double reg=1e-5*g_acc[1];
    out[0]=(float)(bpr+0.2*cl+pr+reg);
    out[1]=(float)bpr;
    out[2]=(float)(0.2*cl);
    out[3]=(float)pr;
  }
}

#define GA(p,s) do{ void* t_=0; cudaGetSymbolAddress(&t_,s); p=(decltype(p))t_; }while(0)

extern "C" void kernel_launch(void* const* d_in, const int* in_sizes, int n_in,
                              void* d_out, int out_size){
  const float* E_u_0 =(const float*)d_in[0];
  const float* E_i_0 =(const float*)d_in[1];
  const float* fuse_w=(const float*)d_in[2];
  const float* fuse_b=(const float*)d_in[3];
  const float* W1u   =(const float*)d_in[4];
  const float* W1i   =(const float*)d_in[5];
  const float* b1    =(const float*)d_in[6];
  const float* W2    =(const float*)d_in[7];
  const float* b2    =(const float*)d_in[8];
  const float* att_a =(const float*)d_in[9];
  const float* wv    =(const float*)d_in[10];
  const float* Wg    =(const float*)d_in[11];
  const float* adj   =(const float*)d_in[12];
  const float* dm    =(const float*)d_in[13];
  const float* da    =(const float*)d_in[14];
  const int* esrc=(const int*)d_in[15];
  const int* edst=(const int*)d_in[16];
  const int* uids=(const int*)d_in[17];
  const int* iids=(const int*)d_in[18];
  const int* pos =(const int*)d_in[19];
  const int* neg =(const int*)d_in[20];
  float* out=(float*)d_out;

  float *Eu1,*EuS,*U1,*Hg,*hu,*Zu,*Ei1,*EiS,*I1,*hi,*Zi,*au,*ai;
  float *wcu,*wci,*wm0u,*wm1u,*wm0i,*wm1i,*wa0u,*wa1u,*wa0i,*wa1i;
  int *rpu,*rpi,*colu,*coli;
  GA(Eu1,g_Eu1); GA(EuS,g_EuS); GA(U1,g_U1); GA(Hg,g_Hg);
  GA(hu,g_hu); GA(Zu,g_Zu); GA(Ei1,g_Ei1); GA(EiS,g_EiS);
  GA(I1,g_I1); GA(hi,g_hi); GA(Zi,g_Zi); GA(au,g_au); GA(ai,g_ai);
  GA(wcu,g_wcu); GA(wci,g_wci); GA(wm0u,g_wm0u); GA(wm1u,g_wm1u);
  GA(wm0i,g_wm0i); GA(wm1i,g_wm1i); GA(wa0u,g_wa0u); GA(wa1u,g_wa1u);
  GA(wa0i,g_wa0i); GA(wa1i,g_wa1i);
  GA(rpu,g_rowptr_u); GA(rpi,g_rowptr_i);
  GA(colu,g_col_u); GA(coli,g_col_i);

  dim3 b256(256), bg(16,16);
  int gU=(NU+15)/16, gI=(NI+15)/16;
  int nbU=(NU+255)/256, nbI=(NI+255)/256;

  k_init<<<391,b256>>>();
  k_count<<<(NE+255)/256,b256>>>(esrc,edst);
  k_scanA<<<nbU+nbI,b256>>>(nbU);
  k_scanB<<<2,512>>>(nbU,nbI);
  k_scanC<<<nbU+nbI,b256>>>(nbU);
  k_fill<<<(NE+255)/256,b256>>>(esrc,edst,adj,dm,fuse_w,fuse_b,wv);

  // U1 / I1 (+att scalars) in one launch
  k_gemm2<<<gU+gI,bg>>>(E_u_0,W1u,b1,att_a,U1,au,NU,
                        E_i_0,W1i,0,att_a+64,I1,ai,NI,gU);

  // main propagation
  k_spmm2<<<gU+gI,b256>>>(rpu,colu,wm0u,E_i_0,0,0,Eu1,NU,
                          rpi,coli,wm0i,E_u_0,0,0,Ei1,NI,gU);
  k_spmm2<<<gU+gI,b256>>>(rpu,colu,wm1u,Ei1,E_u_0,Eu1,EuS,NU,
                          rpi,coli,wm1i,Eu1,E_i_0,Ei1,EiS,NI,gU);
  // GCN view
  k_spmm2<<<gU+gI,b256>>>(rpu,colu,wcu,EiS,0,0,hu,NU,
                          rpi,coli,wci,EuS,0,0,hi,NI,gU);
  k_gemm2<<<gU,bg>>>(hu,Wg,0,0,Hg,0,NU, 0,0,0,0,0,0,0,gU);

  // edge passes
  k_edge1<<<(NI+7)/8,b256>>>(W2,b2);
  k_edge2<<<(NE+255)/256,b256>>>(fuse_w,fuse_b,adj,da);

  // augmented propagation
  k_spmm2<<<gU+gI,b256>>>(rpu,colu,wa0u,E_i_0,0,0,Eu1,NU,
                          rpi,coli,wa0i,E_u_0,0,0,Ei1,NI,gU);
  k_spmm2<<<gU+gI,b256>>>(rpu,colu,wa1u,Ei1,E_u_0,Eu1,Zu,NU,
                          rpi,coli,wa1i,Eu1,E_i_0,Ei1,Zi,NI,gU);

  // losses
  k_sqsum_all<<<512,b256>>>(E_u_0,E_i_0,fuse_w,fuse_b,wv,W1u,W1i,b1,W2,b2,att_a,Wg);
  k_small<<<(BB*32+255)/256,b256>>>(uids,iids,pos,neg);
  int gxU=(NU+63)/64, gxI=(NI+63)/64;
  k_negsum2<<<dim3(gxU+gxI,BB/64),b256>>>(uids,iids,gxU);

  k_final<<<1,1024>>>(out);
}

// round 9
// speedup vs baseline: 2.4920x; 1.0884x over previous
#include <cuda_runtime.h>
#include <cuda_bf16.h>
#include <math.h>

#define NU 100000
#define NI 50000
#define NE 800000
#define BB 1024
typedef unsigned long long ull;

__device__ float g_Eu1[NU*64];
__device__ float g_EuS[NU*64];
__device__ float g_Hg [NU*64];
__device__ float g_hu [NU*64];
__device__ float g_Zu [NU*64];
__device__ float g_Ei1[NI*64];
__device__ float g_EiS[NI*64];
__device__ float g_I1 [NI*64];
__device__ float g_hi [NI*64];
__device__ float g_Zi [NI*64];
__device__ float g_au[NU];
__device__ float g_ai[NI];
// bf16 gather tables
__device__ __nv_bfloat16 g_bEu0[NU*64];
__device__ __nv_bfloat16 g_bEu1[NU*64];
__device__ __nv_bfloat16 g_bEuS[NU*64];
__device__ __nv_bfloat16 g_bU1 [NU*64];
__device__ __nv_bfloat16 g_bHg [NU*64];
__device__ __nv_bfloat16 g_bEi0[NI*64];
__device__ __nv_bfloat16 g_bEi1[NI*64];
__device__ __nv_bfloat16 g_bEiS[NI*64];
__device__ float g_views[4*NE];
__device__ float g_pre[NE];
__device__ int   g_rowptr_u[NU+1];
__device__ int   g_rowptr_i[NI+1];
__device__ int   g_cur_u[NU];
__device__ int   g_cur_i[NI];
__device__ int   g_deg_u[NU];
__device__ int   g_deg_i[NI];
__device__ int   g_part_u[512];
__device__ int   g_part_i[512];
__device__ int   g_col_u[NE];
__device__ int   g_col_i[NE];
__device__ int   g_eid_i[NE];
__device__ int   g_pos_u[NE];
__device__ int   g_pos_i[NE];
__device__ float g_fwi[NE], g_fbi[NE], g_wvi[NE];
__device__ float g_wcu[NE],  g_wci[NE];
__device__ float g_wm0u[NE], g_wm1u[NE];
__device__ float g_wm0i[NE], g_wm1i[NE];
__device__ float g_wa0u[NE], g_wa1u[NE];
__device__ float g_wa0i[NE], g_wa1i[NE];
__device__ double g_expsum[4];
__device__ double g_acc[4];     // 0: pr, 1: reg, 2: bpr, 3: pos
__device__ double g_negS[2*BB];

__device__ __forceinline__ float sigf(float x){ return 1.f/(1.f+__expf(-x)); }
__device__ __forceinline__ float tanha(float x){
  float y; asm("tanh.approx.f32 %0, %1;":"=f"(y):"f"(x)); return y;
}
__device__ __forceinline__ unsigned tf32c(float f){
  unsigned u; asm("cvt.rna.tf32.f32 %0, %1;":"=r"(u):"f"(f)); return u;
}
__device__ __forceinline__ float4 b2f4(uint2 raw){
  __nv_bfloat162 b0=*(__nv_bfloat162*)&raw.x, b1=*(__nv_bfloat162*)&raw.y;
  float2 f0=__bfloat1622float2(b0), f1=__bfloat1622float2(b1);
  return make_float4(f0.x,f0.y,f1.x,f1.y);
}
__device__ __forceinline__ uint2 f4b(float4 v){
  __nv_bfloat162 b0=__float22bfloat162_rn(make_float2(v.x,v.y));
  __nv_bfloat162 b1=__float22bfloat162_rn(make_float2(v.z,v.w));
  uint2 r; r.x=*(unsigned*)&b0; r.y=*(unsigned*)&b1; return r;
}

__global__ void k_init(){
  int i=blockIdx.x*blockDim.x+threadIdx.x, st=gridDim.x*blockDim.x;
  for(int t=i;t<NU;t+=st) g_deg_u[t]=0;
  for(int t=i;t<NI;t+=st) g_deg_i[t]=0;
  for(int t=i;t<2*BB;t+=st) g_negS[t]=0.0;
  if(i<4){ g_expsum[i]=0.0; g_acc[i]=0.0; }
}

__global__ void k_count(const int* __restrict__ src, const int* __restrict__ dst){
  int e=blockIdx.x*blockDim.x+threadIdx.x;
  if(e<NE){ atomicAdd(&g_deg_u[src[e]],1); atomicAdd(&g_deg_i[dst[e]],1); }
}

__global__ void k_scanA(int nbU){
  __shared__ int sh[256];
  int bu=blockIdx.x<nbU;
  const int* deg = bu? g_deg_u : g_deg_i;
  int* part      = bu? g_part_u: g_part_i;
  int blk = bu? blockIdx.x : blockIdx.x-nbU;
  int n = bu? NU:NI;
  int i=blk*256+threadIdx.x;
  sh[threadIdx.x]=(i<n)?deg[i]:0;
  __syncthreads();
  for(int o=128;o;o>>=1){ if(threadIdx.x<o) sh[threadIdx.x]+=sh[threadIdx.x+o]; __syncthreads(); }
  if(threadIdx.x==0) part[blk]=sh[0];
}
__global__ void k_scanB(int nbU, int nbI){
  __shared__ int sh[512];
  int* part = blockIdx.x? g_part_i : g_part_u;
  int nb    = blockIdx.x? nbI : nbU;
  int t=threadIdx.x;
  int v=(t<nb)?part[t]:0;
  sh[t]=v; __syncthreads();
  for(int o=1;o<512;o<<=1){ int a=(t>=o)?sh[t-o]:0; __syncthreads(); sh[t]+=a; __syncthreads(); }
  if(t<nb) part[t]=sh[t]-v;
}
__global__ void k_scanC(int nbU){
  __shared__ int sh[256];
  int bu=blockIdx.x<nbU;
  const int* deg = bu? g_deg_u : g_deg_i;
  const int* part= bu? g_part_u: g_part_i;
  int* rowptr    = bu? g_rowptr_u : g_rowptr_i;
  int* cur       = bu? g_cur_u : g_cur_i;
  int blk = bu? blockIdx.x : blockIdx.x-nbU;
  int n = bu? NU:NI;
  int i=blk*256+threadIdx.x;
  int v=(i<n)?deg[i]:0;
  sh[threadIdx.x]=v; __syncthreads();
  for(int o=1;o<256;o<<=1){ int a=(threadIdx.x>=o)?sh[threadIdx.x-o]:0; __syncthreads(); sh[threadIdx.x]+=a; __syncthreads(); }
  int excl=part[blk]+sh[threadIdx.x]-v;
  if(i<n){ rowptr[i]=excl; cur[i]=excl; }
  if(i==n-1) rowptr[n]=excl+v;
}

__global__ void k_fill(const int* __restrict__ src, const int* __restrict__ dst,
                       const float* __restrict__ adj, const float* __restrict__ dm,
                       const float* __restrict__ fw, const float* __restrict__ fb,
                       const float* __restrict__ wv){
  int e=blockIdx.x*blockDim.x+threadIdx.x;
  const float R=1.3333333333333333f;
  if(e<NE){
    int s=src[e], d=dst[e];
    float w=adj[e];
    float m0u=(dm[e]      >0.25f)? w*R:0.f;
    float m1u=(dm[2*NE+e] >0.25f)? w*R:0.f;
    float m0i=(dm[NE+e]   >0.25f)? w*R:0.f;
    float m1i=(dm[3*NE+e] >0.25f)? w*R:0.f;
    int p=atomicAdd(&g_cur_u[s],1);
    g_col_u[p]=d; g_wcu[p]=w; g_wm0u[p]=m0u; g_wm1u[p]=m1u;
    g_pos_u[e]=p;
    int q=atomicAdd(&g_cur_i[d],1);
    g_col_i[q]=s; g_eid_i[q]=e; g_wci[q]=w; g_wm0i[q]=m0i; g_wm1i[q]=m1i;
    g_fwi[q]=fw[e]; g_fbi[q]=fb[e]; g_wvi[q]=wv[e];
    g_pos_i[e]=q;
  }
}

// SpMM with bf16 gather: Y = A + Bv + sum_j w[j]*X[col[j],:]; optional bf16 out
__device__ __forceinline__ void spmm_body(const int* rowptr, const int* col,
                       const float* w, const __nv_bfloat16* X,
                       const float* A, const float* Bv,
                       float* Y, __nv_bfloat16* Yb, int nrows, int blk){
  int tid=threadIdx.x;
  int warp=tid>>5, lane=tid&31;
  int half=lane>>4, sub=lane&15;
  int r=blk*16 + warp*2 + half;
  int beg=0,end=0;
  if(r<nrows){ beg=rowptr[r]; end=rowptr[r+1]; }
  int deg=end-beg;
  int maxdeg=max(deg,__shfl_xor_sync(0xffffffffu,deg,16));
  float4 aa[4];
  #pragma unroll
  for(int q=0;q<4;q++) aa[q]=make_float4(0.f,0.f,0.f,0.f);
  for(int base=0; base<maxdeg; base+=16){
    int c=0; float v=0.f;
    if(base+sub<deg){
      int j=beg+base+sub;
      c=col[j]; v=w[j];
    }
    #pragma unroll
    for(int q=0;q<16;q++){
      float vq=__shfl_sync(0xffffffffu,v,q,16);
      int   cq=__shfl_sync(0xffffffffu,c,q,16);
      if(vq!=0.f){
        float4 x=b2f4(*(const uint2*)(X+cq*64+sub*4));
        aa[q&3].x+=vq*x.x; aa[q&3].y+=vq*x.y; aa[q&3].z+=vq*x.z; aa[q&3].w+=vq*x.w;
      }
    }
  }
  float4 acc;
  acc.x=(aa[0].x+aa[1].x)+(aa[2].x+aa[3].x);
  acc.y=(aa[0].y+aa[1].y)+(aa[2].y+aa[3].y);
  acc.z=(aa[0].z+aa[1].z)+(aa[2].z+aa[3].z);
  acc.w=(aa[0].w+aa[1].w)+(aa[2].w+aa[3].w);
  if(r<nrows){
    int o=r*64+sub*4;
    if(A){ float4 a=*(const float4*)&A[o]; acc.x+=a.x; acc.y+=a.y; acc.z+=a.z; acc.w+=a.w; }
    if(Bv){ float4 b=*(const float4*)&Bv[o]; acc.x+=b.x; acc.y+=b.y; acc.z+=b.z; acc.w+=b.w; }
    *(float4*)&Y[o]=acc;
    if(Yb) *(uint2*)(Yb+o)=f4b(acc);
  }
}
__global__ void k_spmm2(const int* ra, const int* ca, const float* wa, const __nv_bfloat16* Xa,
                        const float* Aa, const float* Ba, float* Ya, __nv_bfloat16* Yba, int na,
                        const int* rb, const int* cb, const float* wb, const __nv_bfloat16* Xb,
                        const float* Ab, const float* Bb, float* Yb, __nv_bfloat16* Ybb, int nb, int gA){
  if((int)blockIdx.x<gA) spmm_body(ra,ca,wa,Xa,Aa,Ba,Ya,Yba,na,blockIdx.x);
  else                   spmm_body(rb,cb,wb,Xb,Ab,Bb,Yb,Ybb,nb,blockIdx.x-gA);
}

// node GEMM: optional fp32 out, bf16 out, bf16 copy of X, att scalar
__device__ __forceinline__ void gemm_body(const float* X, const float* W,
                            const float* bias, const float* att,
                            float* Y, __nv_bfloat16* Yb, __nv_bfloat16* Xb,
                            float* attOut, int n, int blk){
  __shared__ float Ws[64*64];
  __shared__ float Xs[16][64];
  __shared__ float atts[64];
  int tx=threadIdx.x, ty=threadIdx.y;
  int tid=ty*16+tx;
  for(int t=tid;t<4096;t+=256) Ws[t]=W[t];
  if(att && tid<64) atts[tid]=att[tid];
  int r=blk*16+ty;
  float4 xv4=make_float4(0.f,0.f,0.f,0.f);
  if(r<n){ xv4=((const float4*)&X[r*64])[tx]; ((float4*)Xs[ty])[tx]=xv4; }
  __syncthreads();
  if(r<n){
    if(Xb) *(uint2*)(Xb+r*64+tx*4)=f4b(xv4);
    float4 acc = bias ? ((const float4*)bias)[tx] : make_float4(0.f,0.f,0.f,0.f);
    #pragma unroll
    for(int k=0;k<64;k++){
      float xv=Xs[ty][k];
      float4 w=((const float4*)&Ws[k*64])[tx];
      acc.x+=xv*w.x; acc.y+=xv*w.y; acc.z+=xv*w.z; acc.w+=xv*w.w;
    }
    if(Y) ((float4*)&Y[r*64])[tx]=acc;
    if(Yb) *(uint2*)(Yb+r*64+tx*4)=f4b(acc);
  }
  if(att){
    float p=0.f;
    if(r<n){
      #pragma unroll
      for(int d=0;d<4;d++) p+=Xs[ty][tx*4+d]*atts[tx*4+d];
    }
    #pragma unroll
    for(int o=8;o;o>>=1) p+=__shfl_xor_sync(0xffffffffu,p,o,16);
    if(r<n && tx==0) attOut[r]=p;
  }
}
__global__ void k_gemm2(const float* Xa, const float* Wa, const float* ba, const float* aa,
                        float* Ya, __nv_bfloat16* Yba, __nv_bfloat16* Xba, float* aoa, int na,
                        const float* Xb, const float* Wb, const float* bb, const float* ab,
                        float* Yb, __nv_bfloat16* Ybb, __nv_bfloat16* Xbb, float* aob, int nb, int gA){
  if((int)blockIdx.x<gA) gemm_body(Xa,Wa,ba,aa,Ya,Yba,Xba,aoa,na,blockIdx.x);
  else                   gemm_body(Xb,Wb,bb,ab,Yb,Ybb,Xbb,aob,nb,blockIdx.x-gA);
}

// edge views, CSR-item order: warp per item row, 2 edges x 16 lanes, bf16 gathers
__global__ void k_edge1(const float* __restrict__ W2, const float* __restrict__ b2){
  __shared__ float W2s[64];
  __shared__ double sacc[4];
  int tid=threadIdx.x, lane=tid&31, warp=tid>>5;
  int half=lane>>4, sub=lane&15;
  if(tid<64) W2s[tid]=W2[tid];
  if(tid<4)  sacc[tid]=0.0;
  __syncthreads();
  int r=blockIdx.x*8+warp;
  float e0=0.f,e1=0.f,e2=0.f,e3=0.f;
  if(r<NI){
    float b2v=b2[0];
    float4 w2=((const float4*)W2s)[sub];
    float4 i1=*(const float4*)&g_I1 [r*64+sub*4];
    float4 hi=*(const float4*)&g_hi [r*64+sub*4];
    float4 si=*(const float4*)&g_EiS[r*64+sub*4];
    float aiv=g_ai[r];
    int beg=g_rowptr_i[r], end=g_rowptr_i[r+1];
    for(int j0=beg;j0<end;j0+=2){
      int j=j0+half;
      bool act=(j<end);
      int u=g_col_i[act? j : end-1];
      float4 u1=b2f4(*(const uint2*)(g_bU1 +u*64+sub*4));
      float4 hg=b2f4(*(const uint2*)(g_bHg +u*64+sub*4));
      float4 su=b2f4(*(const uint2*)(g_bEuS+u*64+sub*4));
      float m  = fmaxf(u1.x+i1.x,0.f)*w2.x + fmaxf(u1.y+i1.y,0.f)*w2.y
               + fmaxf(u1.z+i1.z,0.f)*w2.z + fmaxf(u1.w+i1.w,0.f)*w2.w;
      float gc = hg.x*hi.x+hg.y*hi.y+hg.z*hi.z+hg.w*hi.w;
      float pr = su.x*si.x+su.y*si.y+su.z*si.z+su.w*si.w;
      #pragma unroll
      for(int o=8;o;o>>=1){
        m +=__shfl_xor_sync(0xffffffffu,m,o,16);
        gc+=__shfl_xor_sync(0xffffffffu,gc,o,16);
        pr+=__shfl_xor_sync(0xffffffffu,pr,o,16);
      }
      if(act && sub==0){
        int e=g_eid_i[j];
        float v0=sigf(m+b2v);
        float v1=sigf(g_wvi[j]);
        float v2=sigf(gc);
        float a=g_au[u]+aiv;
        float v3=sigf(a>0.f? a : 0.2f*a);
        g_views[e]=v0; g_views[NE+e]=v1; g_views[2*NE+e]=v2; g_views[3*NE+e]=v3;
        g_pre[e]=sigf(pr);
        float w=g_fwi[j], b=g_fbi[j];
        e0+=__expf(tanha(w*v0+b));
        e1+=__expf(tanha(w*v1+b));
        e2+=__expf(tanha(w*v2+b));
        e3+=__expf(tanha(w*v3+b));
      }
    }
  }
  e0+=__shfl_xor_sync(0xffffffffu,e0,16);
  e1+=__shfl_xor_sync(0xffffffffu,e1,16);
  e2+=__shfl_xor_sync(0xffffffffu,e2,16);
  e3+=__shfl_xor_sync(0xffffffffu,e3,16);
  if(lane==0 && r<NI){
    atomicAdd(&sacc[0],(double)e0);
    atomicAdd(&sacc[1],(double)e1);
    atomicAdd(&sacc[2],(double)e2);
    atomicAdd(&sacc[3],(double)e3);
  }
  __syncthreads();
  if(tid<4) atomicAdd(&g_expsum[tid],sacc[tid]);
}

__global__ void k_edge2(const float* __restrict__ fw, const float* __restrict__ fb,
                        const float* __restrict__ adj, const float* __restrict__ da){
  int e=blockIdx.x*blockDim.x+threadIdx.x;
  const float R=1.3333333333333333f;
  float lp=0.f;
  if(e<NE){
    float S0=(float)g_expsum[0], S1=(float)g_expsum[1];
    float S2=(float)g_expsum[2], S3=(float)g_expsum[3];
    float w=fw[e], b=fb[e];
    float v0=g_views[e], v1=g_views[NE+e], v2=g_views[2*NE+e], v3=g_views[3*NE+e];
    float Ag = __expf(tanha(w*v0+b))/S0*v0
             + __expf(tanha(w*v1+b))/S1*v1
             + __expf(tanha(w*v2+b))/S2*v2
             + __expf(tanha(w*v3+b))/S3*v3;
    float sumv=v0+v1+v2+v3;
    float baew=g_pre[e]*((sumv-3.f*Ag)*0.2f);
    float augw=baew*adj[e];
    int pu=g_pos_u[e], pi=g_pos_i[e];
    g_wa0u[pu]=(da[e]      >0.25f)? augw*R:0.f;
    g_wa1u[pu]=(da[2*NE+e] >0.25f)? augw*R:0.f;
    g_wa0i[pi]=(da[NE+e]   >0.25f)? augw*R:0.f;
    g_wa1i[pi]=(da[3*NE+e] >0.25f)? augw*R:0.f;
    lp=-__logf(baew);
  }
  #pragma unroll
  for(int o=16;o;o>>=1) lp += __shfl_xor_sync(0xffffffffu,lp,o);
  if((threadIdx.x&31)==0) atomicAdd(&g_acc[0],(double)lp);
}

__global__ void k_sqsum_all(const float* __restrict__ Eu0, const float* __restrict__ Ei0,
                            const float* __restrict__ fw, const float* __restrict__ fb,
                            const float* __restrict__ wv,
                            const float* __restrict__ W1u, const float* __restrict__ W1i,
                            const float* __restrict__ b1, const float* __restrict__ W2,
                            const float* __restrict__ b2, const float* __restrict__ att_a,
                            const float* __restrict__ Wg){
  double s=0.0;
  int i0=blockIdx.x*blockDim.x+threadIdx.x, st=gridDim.x*blockDim.x;
  for(int i=i0;i<NU*64;i+=st){ float v=Eu0[i]; s+=(double)v*(double)v; }
  for(int i=i0;i<NI*64;i+=st){ float v=Ei0[i]; s+=(double)v*(double)v; }
  for(int i=i0;i<NE;i+=st){
    float x=fw[i],y=fb[i],z=wv[i];
    s+=(double)x*x+(double)y*y+(double)z*z;
  }
  if(blockIdx.x==0){
    const float* ps[7]={W1u,W1i,b1,W2,b2,att_a,Wg};
    const int    ln[7]={4096,4096,64,64,1,128,4096};
    for(int a=0;a<7;a++){
      const float* p=ps[a];
      for(int i=threadIdx.x;i<ln[a];i+=blockDim.x){ float v=p[i]; s+=(double)v*(double)v; }
    }
  }
  #pragma unroll
  for(int o=16;o;o>>=1) s += __shfl_xor_sync(0xffffffffu,s,o);
  if((threadIdx.x&31)==0) atomicAdd(&g_acc[1],s);
}

__global__ void k_small(const int* __restrict__ uids, const int* __restrict__ iids,
                        const int* __restrict__ pos, const int* __restrict__ neg){
  int w=(blockIdx.x*blockDim.x+threadIdx.x)>>5;
  int l=threadIdx.x&31;
  if(w>=BB) return;
  int u=uids[w], it=iids[w], p=pos[w], ng=neg[w];
  float dzu=0,dzi=0,dup=0,dun=0;
  #pragma unroll
  for(int d=l; d<64; d+=32){
    float eu=g_EuS[u*64+d];
    dzu += g_Zu[u*64+d]*eu;
    dzi += g_Zi[it*64+d]*g_EiS[it*64+d];
    dup += eu*g_EiS[p*64+d];
    dun += eu*g_EiS[ng*64+d];
  }
  #pragma unroll
  for(int o=16;o;o>>=1){
    dzu+=__shfl_xor_sync(0xffffffffu,dzu,o);
    dzi+=__shfl_xor_sync(0xffffffffu,dzi,o);
    dup+=__shfl_xor_sync(0xffffffffu,dup,o);
    dun+=__shfl_xor_sync(0xffffffffu,dun,o);
  }
  if(l==0){
    float cu=fminf(fmaxf(dzu*5.f,-5.f),5.f);
    float ci=fminf(fmaxf(dzi*5.f,-5.f),5.f);
    float diff=dup-dun;
    float bpr=fmaxf(-diff,0.f)+log1pf(expf(-fabsf(diff)));
    atomicAdd(&g_acc[3],(double)(cu+ci));
    atomicAdd(&g_acc[2],(double)bpr);
  }
}

__device__ __forceinline__ void negsum_body(const int* ids, const float* Z,
                                            const float* X, int N, int isItem, int bx){
  __shared__ unsigned Gs[64][68];
  __shared__ unsigned Xs[64][68];
  __shared__ float Ps[64][8];
  int b0=blockIdx.y*64, j0=bx*64;
  int tid=threadIdx.x;
  const float scale=7.213475204444817f; // log2(e)/0.2
  for(int idx=tid; idx<64*16; idx+=256){
    int r=idx>>4, c4=(idx&15)*4;
    float4 g=*(const float4*)&Z[ids[b0+r]*64+c4];
    Gs[r][c4+0]=tf32c(g.x*scale); Gs[r][c4+1]=tf32c(g.y*scale);
    Gs[r][c4+2]=tf32c(g.z*scale); Gs[r][c4+3]=tf32c(g.w*scale);
    int j=j0+r;
    float4 x = (j<N)? *(const float4*)&X[j*64+c4] : make_float4(0.f,0.f,0.f,0.f);
    Xs[r][c4+0]=tf32c(x.x); Xs[r][c4+1]=tf32c(x.y);
    Xs[r][c4+2]=tf32c(x.z); Xs[r][c4+3]=tf32c(x.w);
  }
  __syncthreads();
  int w=tid>>5, lane=tid&31;
  int g=lane>>2, t=lane&3;
  int brow=(w&3)*16, jbase=(w>>2)*32;
  float c[4][4];
  #pragma unroll
  for(int nt=0;nt<4;nt++)
    #pragma unroll
    for(int q=0;q<4;q++) c[nt][q]=0.f;
  #pragma unroll
  for(int k0=0;k0<64;k0+=8){
    unsigned a0=Gs[brow+g][k0+t],   a1=Gs[brow+g+8][k0+t];
    unsigned a2=Gs[brow+g][k0+t+4], a3=Gs[brow+g+8][k0+t+4];
    #pragma unroll
    for(int nt=0;nt<4;nt++){
      unsigned bb0=Xs[jbase+nt*8+g][k0+t], bb1=Xs[jbase+nt*8+g][k0+t+4];
      asm volatile("mma.sync.aligned.m16n8k8.row.col.f32.tf32.tf32.f32 "
        "{%0,%1,%2,%3}, {%4,%5,%6,%7}, {%8,%9}, {%0,%1,%2,%3};"
        : "+f"(c[nt][0]),"+f"(c[nt][1]),"+f"(c[nt][2]),"+f"(c[nt][3])
        : "r"(a0),"r"(a1),"r"(a2),"r"(a3),"r"(bb0),"r"(bb1));
    }
  }
  float s0=0.f, s1=0.f;
  #pragma unroll
  for(int nt=0;nt<4;nt++){
    int col=j0+jbase+nt*8+2*t;
    if(col<N)   { s0+=exp2f(c[nt][0]); s1+=exp2f(c[nt][2]); }
    if(col+1<N) { s0+=exp2f(c[nt][1]); s1+=exp2f(c[nt][3]); }
  }
  int slot=(w>>2)*4+t;
  Ps[brow+g][slot]=s0;
  Ps[brow+g+8][slot]=s1;
  __syncthreads();
  if(tid<64){
    float s=0.f;
    #pragma unroll
    for(int q=0;q<8;q++) s+=Ps[tid][q];
    atomicAdd(&g_negS[isItem*BB + b0 + tid],(double)s);
  }
}
__global__ void k_negsum2(const int* uids, const int* iids, int gxU){
  if((int)blockIdx.x<gxU) negsum_body(uids,g_Zu,g_EuS,NU,0,blockIdx.x);
  else                    negsum_body(iids,g_Zi,g_EiS,NI,1,blockIdx.x-gxU);
}

__global__ void k_final(float* __restrict__ out){
  __shared__ double sh[1024];
  int t=threadIdx.x;
  sh[t]=log(g_negS[t]+1e-8)+log(g_negS[BB+t]+1e-8);
  __syncthreads();
  for(int o=512;o;o>>=1){ if(t<o) sh[t]+=sh[t+o]; __syncthreads(); }
  if(t==0){
    double neg=sh[0]/(double)BB;
    double pos=g_acc[3]/(double)BB;
    double cl=-pos+neg;
    double bpr=g_acc[2]/(double)BB;
    double pr=0.01*(g_acc[0]/(double)NE);
    double reg=1e-5*g_acc[1];
    out[0]=(float)(bpr+0.2*cl+pr+reg);
    out[1]=(float)bpr;
    out[2]=(float)(0.2*cl);
    out[3]=(float)pr;
  }
}

#define GA(p,s) do{ void* t_=0; cudaGetSymbolAddress(&t_,s); p=(decltype(p))t_; }while(0)

extern "C" void kernel_launch(void* const* d_in, const int* in_sizes, int n_in,
                              void* d_out, int out_size){
  const float* E_u_0 =(const float*)d_in[0];
  const float* E_i_0 =(const float*)d_in[1];
  const float* fuse_w=(const float*)d_in[2];
  const float* fuse_b=(const float*)d_in[3];
  const float* W1u   =(const float*)d_in[4];
  const float* W1i   =(const float*)d_in[5];
  const float* b1    =(const float*)d_in[6];
  const float* W2    =(const float*)d_in[7];
  const float* b2    =(const float*)d_in[8];
  const float* att_a =(const float*)d_in[9];
  const float* wv    =(const float*)d_in[10];
  const float* Wg    =(const float*)d_in[11];
  const float* adj   =(const float*)d_in[12];
  const float* dm    =(const float*)d_in[13];
  const float* da    =(const float*)d_in[14];
  const int* esrc=(const int*)d_in[15];
  const int* edst=(const int*)d_in[16];
  const int* uids=(const int*)d_in[17];
  const int* iids=(const int*)d_in[18];
  const int* pos =(const int*)d_in[19];
  const int* neg =(const int*)d_in[20];
  float* out=(float*)d_out;

  float *Eu1,*EuS,*Hg,*hu,*Zu,*Ei1,*EiS,*I1,*hi,*Zi,*au,*ai;
  float *wcu,*wci,*wm0u,*wm1u,*wm0i,*wm1i,*wa0u,*wa1u,*wa0i,*wa1i;
  __nv_bfloat16 *bEu0,*bEu1,*bEuS,*bU1,*bHg,*bEi0,*bEi1,*bEiS;
  int *rpu,*rpi,*colu,*coli;
  GA(Eu1,g_Eu1); GA(EuS,g_EuS); GA(Hg,g_Hg);
  GA(hu,g_hu); GA(Zu,g_Zu); GA(Ei1,g_Ei1); GA(EiS,g_EiS);
  GA(I1,g_I1); GA(hi,g_hi); GA(Zi,g_Zi); GA(au,g_au); GA(ai,g_ai);
  GA(bEu0,g_bEu0); GA(bEu1,g_bEu1); GA(bEuS,g_bEuS); GA(bU1,g_bU1); GA(bHg,g_bHg);
  GA(bEi0,g_bEi0); GA(bEi1,g_bEi1); GA(bEiS,g_bEiS);
  GA(wcu,g_wcu); GA(wci,g_wci); GA(wm0u,g_wm0u); GA(wm1u,g_wm1u);
  GA(wm0i,g_wm0i); GA(wm1i,g_wm1i); GA(wa0u,g_wa0u); GA(wa1u,g_wa1u);
  GA(wa0i,g_wa0i); GA(wa1i,g_wa1i);
  GA(rpu,g_rowptr_u); GA(rpi,g_rowptr_i);
  GA(colu,g_col_u); GA(coli,g_col_i);

  dim3 b256(256), bg(16,16);
  int gU=(NU+15)/16, gI=(NI+15)/16;
  int nbU=(NU+255)/256, nbI=(NI+255)/256;

  k_init<<<391,b256>>>();
  k_count<<<(NE+255)/256,b256>>>(esrc,edst);
  k_scanA<<<nbU+nbI,b256>>>(nbU);
  k_scanB<<<2,512>>>(nbU,nbI);
  k_scanC<<<nbU+nbI,b256>>>(nbU);
  k_fill<<<(NE+255)/256,b256>>>(esrc,edst,adj,dm,fuse_w,fuse_b,wv);

  // U1(bf16)+bEu0+att_u  |  I1(fp32)+bEi0+att_i
  k_gemm2<<<gU+gI,bg>>>(E_u_0,W1u,b1,att_a, 0,bU1,bEu0,au,NU,
                        E_i_0,W1i,0,att_a+64, I1,0,bEi0,ai,NI,gU);

  // main propagation
  k_spmm2<<<gU+gI,b256>>>(rpu,colu,wm0u,bEi0,0,0,Eu1,bEu1,NU,
                          rpi,coli,wm0i,bEu0,0,0,Ei1,bEi1,NI,gU);
  k_spmm2<<<gU+gI,b256>>>(rpu,colu,wm1u,bEi1,E_u_0,Eu1,EuS,bEuS,NU,
                          rpi,coli,wm1i,bEu1,E_i_0,Ei1,EiS,bEiS,NI,gU);
  // GCN view
  k_spmm2<<<gU+gI,b256>>>(rpu,colu,wcu,bEiS,0,0,hu,0,NU,
                          rpi,coli,wci,bEuS,0,0,hi,0,NI,gU);
  k_gemm2<<<gU,bg>>>(hu,Wg,0,0, 0,bHg,0,0,NU, 0,0,0,0,0,0,0,0,0,gU);

  // edge passes
  k_edge1<<<(NI+7)/8,b256>>>(W2,b2);
  k_edge2<<<(NE+255)/256,b256>>>(fuse_w,fuse_b,adj,da);

  // augmented propagation
  k_spmm2<<<gU+gI,b256>>>(rpu,colu,wa0u,bEi0,0,0,Eu1,bEu1,NU,
                          rpi,coli,wa0i,bEu0,0,0,Ei1,bEi1,NI,gU);
  k_spmm2<<<gU+gI,b256>>>(rpu,colu,wa1u,bEi1,E_u_0,Eu1,Zu,0,NU,
                          rpi,coli,wa1i,bEu1,E_i_0,Ei1,Zi,0,NI,gU);

  // losses
  k_sqsum_all<<<512,b256>>>(E_u_0,E_i_0,fuse_w,fuse_b,wv,W1u,W1i,b1,W2,b2,att_a,Wg);
  k_small<<<(BB*32+255)/256,b256>>>(uids,iids,pos,neg);
  int gxU=(NU+63)/64, gxI=(NI+63)/64;
  k_negsum2<<<dim3(gxU+gxI,BB/64),b256>>>(uids,iids,gxU);

  k_final<<<1,1024>>>(out);
}